// round 1
// baseline (speedup 1.0000x reference)
#include <cuda_runtime.h>

#define M_NODES 1024
#define NF 64
#define HID 64
#define BI 4
#define TJ 64
#define NTHREADS 256

// scratch (no cudaMalloc allowed)
__device__ float g_Pi[M_NODES * HID];
__device__ float g_Pj[M_NODES * HID];

typedef unsigned long long ull;

__device__ __forceinline__ ull pack2(float lo, float hi) {
    ull r; asm("mov.b64 %0, {%1,%2};" : "=l"(r) : "f"(lo), "f"(hi)); return r;
}
__device__ __forceinline__ void unpack2(ull v, float& lo, float& hi) {
    asm("mov.b64 {%0,%1}, %2;" : "=f"(lo), "=f"(hi) : "l"(v));
}
__device__ __forceinline__ ull fma2(ull a, ull b, ull c) {
    ull d; asm("fma.rn.f32x2 %0, %1, %2, %3;" : "=l"(d) : "l"(a), "l"(b), "l"(c)); return d;
}
__device__ __forceinline__ float silu(float v) {
    // x * sigmoid(x) = x / (1 + e^-x); MUFU ex2 + MUFU rcp, ~1e-6 rel err
    return __fdividef(v, 1.0f + __expf(-v));
}

// ---------------------------------------------------------------------------
// Precompute Pi = h @ We1[:64] + be1, Pj = h @ We1[64:128]
// ---------------------------------------------------------------------------
__global__ void prep_kernel(const float* __restrict__ h,
                            const float* __restrict__ We1,
                            const float* __restrict__ be1) {
    int idx = blockIdx.x * blockDim.x + threadIdx.x;  // 65536 threads
    int i = idx >> 6, c = idx & 63;
    const float* hr = h + i * NF;
    float pi = be1[c], pj = 0.f;
#pragma unroll 16
    for (int k = 0; k < NF; k++) {
        float hv = hr[k];
        pi = fmaf(hv, We1[k * HID + c], pi);
        pj = fmaf(hv, We1[(NF + k) * HID + c], pj);
    }
    g_Pi[idx] = pi;
    g_Pj[idx] = pj;
}

// ---------------------------------------------------------------------------
// Fused main kernel: one block = 4 node rows (i), loops all j in tiles of 64.
// One thread = one (i,j) edge per tile iteration.
// ---------------------------------------------------------------------------
// shared layout (floats):
//  We2s 4096 | Wx1s 4096 | Pjs 64*65 | Ms 256*65 | Pis 256 | s_sh 256 |
//  xjs 192 | wds 64 | was 64 | be2s 64 | bx1s 64 | wx2s 64 | mis 256 | hids 256
#define SM_FLOATS (4096 + 4096 + 64*65 + 256*65 + 256 + 256 + 192 + 64*5 + 256 + 256)
#define SMEM_BYTES (SM_FLOATS * 4)

__global__ void __launch_bounds__(NTHREADS, 1)
ecnn_main(const float* __restrict__ x, const float* __restrict__ a,
          const float* __restrict__ h, const float* __restrict__ We1,
          const float* __restrict__ We2, const float* __restrict__ be2,
          const float* __restrict__ Wx1, const float* __restrict__ bx1,
          const float* __restrict__ Wx2, const float* __restrict__ bx2,
          const float* __restrict__ Wh1, const float* __restrict__ bh1,
          const float* __restrict__ Wh2, const float* __restrict__ bh2,
          float* __restrict__ out) {
    extern __shared__ float sm[];
    float* We2s = sm;                       // 4096
    float* Wx1s = sm + 4096;                // 4096
    float* Pjs  = sm + 8192;                // 64*65 = 4160  (padded rows)
    float* Ms   = sm + 8192 + 4160;         // 256*65 = 16640 (padded rows)
    float* Pis  = Ms + 16640;               // 256
    float* s_sh = Pis + 256;                // 256
    float* xjs  = s_sh + 256;               // 192
    float* wds  = xjs + 192;                // 64
    float* was  = wds + 64;                 // 64
    float* be2s = was + 64;                 // 64
    float* bx1s = be2s + 64;                // 64
    float* wx2s = bx1s + 64;                // 64
    float* mis  = wx2s + 64;                // 256
    float* hids = mis + 256;                // 256

    const int tid = threadIdx.x;
    const int ibase = blockIdx.x * BI;
    const int i_l = tid >> 6;   // 0..3
    const int jl  = tid & 63;   // 0..63
    const int i_g = ibase + i_l;

    for (int idx = tid; idx < 4096; idx += NTHREADS) {
        We2s[idx] = We2[idx];
        Wx1s[idx] = Wx1[idx];
    }
    if (tid < 64) {
        wds[tid]  = We1[128 * 64 + tid];
        was[tid]  = We1[129 * 64 + tid];
        be2s[tid] = be2[tid];
        bx1s[tid] = bx1[tid];
        wx2s[tid] = Wx2[tid];
    }
    Pis[tid] = g_Pi[ibase * 64 + tid];   // 256 = BI*64 exactly
    __syncthreads();

    const float xi0 = x[i_g * 3 + 0];
    const float xi1 = x[i_g * 3 + 1];
    const float xi2 = x[i_g * 3 + 2];
    const float bx2v = bx2[0];
    const float* arow = a + (size_t)i_g * M_NODES;

    float macc = 0.f;   // owns m_i[i_l][c=jl]
    float xacc = 0.f;   // valid when jl < 3 (dimension d = jl)

    for (int jbase = 0; jbase < M_NODES; jbase += TJ) {
        __syncthreads();  // protect Pjs/xjs/Ms/s_sh reuse vs previous reduction
        for (int idx = tid; idx < TJ * 64; idx += NTHREADS) {
            int r = idx >> 6, c = idx & 63;
            Pjs[r * 65 + c] = g_Pj[(jbase + r) * 64 + c];
        }
        if (tid < TJ * 3) xjs[tid] = x[jbase * 3 + tid];
        __syncthreads();

        const int j = jbase + jl;
        const float dx0 = xi0 - xjs[jl * 3 + 0];
        const float dx1 = xi1 - xjs[jl * 3 + 1];
        const float dx2 = xi2 - xjs[jl * 3 + 2];
        const float d2 = dx0 * dx0 + dx1 * dx1 + dx2 * dx2;
        const float aij = arow[j];

        // pre = Pi + Pj + d2*wd + a*wa  (be1 folded into Pi); t = silu(pre)
        float t[64];
        const float* PiR = Pis + i_l * 64;
        const float* PjR = Pjs + jl * 65;
#pragma unroll
        for (int k = 0; k < 64; k++) {
            float pre = PiR[k] + PjR[k];
            pre = fmaf(d2, wds[k], pre);
            pre = fmaf(aij, was[k], pre);
            t[k] = silu(pre);
        }

        // m = silu(t @ We2 + be2) : packed f32x2 FMA, weights broadcast from SMEM
        ull acc[32];
#pragma unroll
        for (int p = 0; p < 32; p++) acc[p] = *(const ull*)&be2s[2 * p];
#pragma unroll
        for (int k = 0; k < 64; k++) {
            ull tk = pack2(t[k], t[k]);
            const ull* wr = (const ull*)&We2s[k * 64];
#pragma unroll
            for (int q = 0; q < 32; q++) acc[q] = fma2(tk, wr[q], acc[q]);
        }
        float m[64];
#pragma unroll
        for (int p = 0; p < 32; p++) {
            float lo, hi; unpack2(acc[p], lo, hi);
            m[2 * p] = silu(lo);
            m[2 * p + 1] = silu(hi);
        }

        // u = silu(m @ Wx1 + bx1); s = u . Wx2 + bx2
#pragma unroll
        for (int p = 0; p < 32; p++) acc[p] = *(const ull*)&bx1s[2 * p];
#pragma unroll
        for (int k = 0; k < 64; k++) {
            ull mk = pack2(m[k], m[k]);
            const ull* wr = (const ull*)&Wx1s[k * 64];
#pragma unroll
            for (int q = 0; q < 32; q++) acc[q] = fma2(mk, wr[q], acc[q]);
        }
        float s = bx2v;
#pragma unroll
        for (int p = 0; p < 32; p++) {
            float lo, hi; unpack2(acc[p], lo, hi);
            s = fmaf(silu(lo), wx2s[2 * p], s);
            s = fmaf(silu(hi), wx2s[2 * p + 1], s);
        }

        const bool diag = (j == i_g);
        s_sh[tid] = diag ? 0.f : s;
        float* Mr = Ms + tid * 65;
#pragma unroll
        for (int c = 0; c < 64; c++) Mr[c] = diag ? 0.f : m[c];
        __syncthreads();

        // m_i partial reduction: thread (i_l, c=jl) sums its 64 tile-j entries
        {
            const float* base = Ms + (i_l * 64) * 65 + jl;
            float sum = 0.f;
#pragma unroll 8
            for (int r = 0; r < 64; r++) sum += base[r * 65];
            macc += sum;
        }
        // coordinate reduction: threads jl<3 own dimension d for row i_l
        if (jl < 3) {
            const int d = jl;
            const float xi_d = (d == 0) ? xi0 : ((d == 1) ? xi1 : xi2);
            const float* sp = s_sh + i_l * 64;
            float sum = 0.f;
#pragma unroll 8
            for (int r = 0; r < 64; r++) sum += (xi_d - xjs[r * 3 + d]) * sp[r];
            xacc += sum;
        }
    }

    // x_new
    if (jl < 3) {
        const float C = 1.0f / (float)(M_NODES - 1);
        const float xi_d = (jl == 0) ? xi0 : ((jl == 1) ? xi1 : xi2);
        out[i_g * 3 + jl] = fmaf(C, xacc, xi_d);
    }

    // h_new = silu([h, m_i] @ Wh1 + bh1) @ Wh2 + bh2
    mis[tid] = macc;  // mis[i_l*64 + c]
    __syncthreads();
    {
        const int c = jl;
        float acc1 = bh1[c];
        const float* hr = h + i_g * 64;
        const float* mir = mis + i_l * 64;
#pragma unroll 8
        for (int k = 0; k < 64; k++) acc1 = fmaf(hr[k], Wh1[k * 64 + c], acc1);
#pragma unroll 8
        for (int k = 0; k < 64; k++) acc1 = fmaf(mir[k], Wh1[(64 + k) * 64 + c], acc1);
        hids[tid] = silu(acc1);
    }
    __syncthreads();
    {
        const int c = jl;
        float acc2 = bh2[c];
        const float* hidr = hids + i_l * 64;
#pragma unroll 8
        for (int k = 0; k < 64; k++) acc2 = fmaf(hidr[k], Wh2[k * 64 + c], acc2);
        out[3 * M_NODES + i_g * 64 + c] = acc2;
    }
}

extern "C" void kernel_launch(void* const* d_in, const int* in_sizes, int n_in,
                              void* d_out, int out_size) {
    const float* x   = (const float*)d_in[0];
    const float* a   = (const float*)d_in[1];
    const float* h   = (const float*)d_in[2];
    const float* We1 = (const float*)d_in[3];
    const float* be1 = (const float*)d_in[4];
    const float* We2 = (const float*)d_in[5];
    const float* be2 = (const float*)d_in[6];
    const float* Wx1 = (const float*)d_in[7];
    const float* bx1 = (const float*)d_in[8];
    const float* Wx2 = (const float*)d_in[9];
    const float* bx2 = (const float*)d_in[10];
    const float* Wh1 = (const float*)d_in[11];
    const float* bh1 = (const float*)d_in[12];
    const float* Wh2 = (const float*)d_in[13];
    const float* bh2 = (const float*)d_in[14];
    float* out = (float*)d_out;

    cudaFuncSetAttribute(ecnn_main, cudaFuncAttributeMaxDynamicSharedMemorySize,
                         SMEM_BYTES);

    prep_kernel<<<(M_NODES * HID) / NTHREADS, NTHREADS>>>(h, We1, be1);
    ecnn_main<<<M_NODES / BI, NTHREADS, SMEM_BYTES>>>(
        x, a, h, We1, We2, be2, Wx1, bx1, Wx2, bx2, Wh1, bh1, Wh2, bh2, out);
}

// round 2
// speedup vs baseline: 2.3073x; 2.3073x over previous
#include <cuda_runtime.h>
#include <cstdint>

#define M_NODES 1024
#define BI 2
#define TJ 128
#define NTH 256

// scratch (no cudaMalloc allowed)
__device__ float g_Pi[M_NODES * 64];
__device__ float g_Pj[M_NODES * 64];

__device__ __forceinline__ uint32_t f2tf(float f) {
    uint32_t r; asm("cvt.rna.tf32.f32 %0, %1;" : "=r"(r) : "f"(f)); return r;
}
__device__ __forceinline__ float frcp(float f) {
    float r; asm("rcp.approx.f32 %0, %1;" : "=f"(r) : "f"(f)); return r;
}
__device__ __forceinline__ float fex2(float f) {
    float r; asm("ex2.approx.f32 %0, %1;" : "=f"(r) : "f"(f)); return r;
}

#define NLOG2E (-1.4426950408889634f)

// Pairwise silu: 2x ex2 + 1x rcp (3 MUFU per 2 values instead of 4).
__device__ __forceinline__ void silu2(float p0, float p1, float& o0, float& o1) {
    p0 = fmaxf(p0, -80.f);
    p1 = fmaxf(p1, -80.f);
    float e0 = fex2(NLOG2E * p0);
    float e1 = fex2(NLOG2E * p1);
    float s0 = 1.f + e0, s1 = 1.f + e1;
    float inv = frcp(s0 * s1);
    o0 = p0 * (inv * s1);
    o1 = p1 * (inv * s0);
}
__device__ __forceinline__ float silu1(float v) {
    v = fmaxf(v, -80.f);
    return v * frcp(1.f + fex2(NLOG2E * v));
}

__device__ __forceinline__ void mma8(float* c, const uint32_t* a, const uint32_t* b) {
    asm volatile(
        "mma.sync.aligned.m16n8k8.row.col.f32.tf32.tf32.f32 "
        "{%0,%1,%2,%3}, {%4,%5,%6,%7}, {%8,%9}, {%0,%1,%2,%3};"
        : "+f"(c[0]), "+f"(c[1]), "+f"(c[2]), "+f"(c[3])
        : "r"(a[0]), "r"(a[1]), "r"(a[2]), "r"(a[3]), "r"(b[0]), "r"(b[1]));
}

// ---------------------------------------------------------------------------
// Precompute Pi = h @ We1[:64] + be1, Pj = h @ We1[64:128]
// ---------------------------------------------------------------------------
__global__ void prep_kernel(const float* __restrict__ h,
                            const float* __restrict__ We1,
                            const float* __restrict__ be1) {
    int idx = blockIdx.x * blockDim.x + threadIdx.x;
    int i = idx >> 6, c = idx & 63;
    const float* hr = h + i * 64;
    float pi = be1[c], pj = 0.f;
#pragma unroll 16
    for (int k = 0; k < 64; k++) {
        float hv = hr[k];
        pi = fmaf(hv, We1[k * 64 + c], pi);
        pj = fmaf(hv, We1[(64 + k) * 64 + c], pj);
    }
    g_Pi[idx] = pi;
    g_Pj[idx] = pj;
}

// ---------------------------------------------------------------------------
// Warp-level GEMM: [own 32 rows of Ts (tf32)] @ Wt[64x64 transposed, tf32]
// via m16n8k8 tf32 mma.sync. acc initialized with bias (per output column).
// ---------------------------------------------------------------------------
__device__ __forceinline__ void do_gemm(const uint32_t* __restrict__ Ts,
                                        const uint32_t* __restrict__ Wt,
                                        const float* __restrict__ bias,
                                        float acc[2][8][4],
                                        int wrow, int g, int t4) {
#pragma unroll
    for (int mt = 0; mt < 2; mt++)
#pragma unroll
        for (int nt = 0; nt < 8; nt++) {
            float b0 = bias[nt * 8 + t4 * 2];
            float b1 = bias[nt * 8 + t4 * 2 + 1];
            acc[mt][nt][0] = b0; acc[mt][nt][1] = b1;
            acc[mt][nt][2] = b0; acc[mt][nt][3] = b1;
        }
#pragma unroll
    for (int kt = 0; kt < 8; kt++) {
        const int kc = kt * 8 + t4;
        uint32_t A[2][4], B[8][2];
#pragma unroll
        for (int mt = 0; mt < 2; mt++) {
            const uint32_t* r0 = Ts + (wrow + mt * 16 + g) * 68;
            A[mt][0] = r0[kc];
            A[mt][1] = r0[8 * 68 + kc];
            A[mt][2] = r0[kc + 4];
            A[mt][3] = r0[8 * 68 + kc + 4];
        }
#pragma unroll
        for (int nt = 0; nt < 8; nt++) {
            const uint32_t* bp = Wt + (nt * 8 + g) * 68 + kc;
            B[nt][0] = bp[0];
            B[nt][1] = bp[4];
        }
#pragma unroll
        for (int mt = 0; mt < 2; mt++)
#pragma unroll
            for (int nt = 0; nt < 8; nt++)
                mma8(acc[mt][nt], A[mt], B[nt]);
    }
}

// ---------------------------------------------------------------------------
// Fused main kernel: block = 2 i-rows, j-tiles of 128 -> 256-edge GEMM tiles.
// Warp w owns tile rows [32w, 32w+32): the entire j-loop is warp-synchronous.
// ---------------------------------------------------------------------------
// SMEM (u32 words): Ts 256*68=17408 | Wt2 4352 | Wt1 4352 | floats:
// Pi_s 128 | wds 64 | was 64 | be2s 64 | bx1s 64 | wx2s 64 | s_sh 256 |
// mired 512 | mi_s 128 | hids 128 | xred 24   => 27608 words = 110432 B
#define SMEM_BYTES (27608 * 4)

__global__ void __launch_bounds__(NTH, 1)
ecnn_main(const float* __restrict__ x, const float* __restrict__ a,
          const float* __restrict__ h, const float* __restrict__ We1,
          const float* __restrict__ We2, const float* __restrict__ be2,
          const float* __restrict__ Wx1, const float* __restrict__ bx1,
          const float* __restrict__ Wx2, const float* __restrict__ bx2,
          const float* __restrict__ Wh1, const float* __restrict__ bh1,
          const float* __restrict__ Wh2, const float* __restrict__ bh2,
          float* __restrict__ out) {
    extern __shared__ uint32_t sm[];
    uint32_t* Ts  = sm;
    uint32_t* Wt2 = sm + 17408;
    uint32_t* Wt1 = sm + 21760;
    float* fsm  = (float*)(sm + 26112);
    float* Pi_s = fsm;          // 128
    float* wds  = fsm + 128;    // 64
    float* was  = fsm + 192;    // 64
    float* be2s = fsm + 256;    // 64
    float* bx1s = fsm + 320;    // 64
    float* wx2s = fsm + 384;    // 64
    float* s_sh = fsm + 448;    // 256
    float* mired= fsm + 704;    // 8*64
    float* mi_s = fsm + 1216;   // 128
    float* hids = fsm + 1344;   // 128
    float* xred = fsm + 1472;   // 24

    const int tid  = threadIdx.x;
    const int lane = tid & 31;
    const int warp = tid >> 5;
    const int wrow = warp << 5;
    const int g    = lane >> 2;
    const int t4   = lane & 3;
    const int ibase = blockIdx.x * BI;

    // stage transposed tf32 weights + small vectors
    for (int idx = tid; idx < 4096; idx += NTH) {
        int k = idx >> 6, n = idx & 63;
        Wt2[n * 68 + k] = f2tf(We2[idx]);
        Wt1[n * 68 + k] = f2tf(Wx1[idx]);
    }
    if (tid < 64) {
        wds[tid]  = We1[128 * 64 + tid];
        was[tid]  = We1[129 * 64 + tid];
        be2s[tid] = be2[tid];
        bx1s[tid] = bx1[tid];
        wx2s[tid] = Wx2[tid];
    }
    if (tid < 128) Pi_s[tid] = g_Pi[ibase * 64 + tid];
    __syncthreads();

    const int il_e = tid >> 7;            // which of the 2 i-rows this edge-thread owns
    const int jl   = tid & 127;
    const int ig_e = ibase + il_e;
    const float xi0 = x[ig_e * 3 + 0];
    const float xi1 = x[ig_e * 3 + 1];
    const float xi2 = x[ig_e * 3 + 2];
    const float bx2v = bx2[0];
    const float* arow = a + (size_t)ig_e * M_NODES;
    const int igw = ibase + (warp >> 2); // i-row of this warp's gemm rows

    float macc[16];
#pragma unroll
    for (int q = 0; q < 16; q++) macc[q] = 0.f;
    float xa0 = 0.f, xa1 = 0.f, xa2 = 0.f;

    for (int jb = 0; jb < M_NODES; jb += TJ) {
        __syncwarp();   // previous iter's Ts reads (own warp rows) done
        // ---------------- phase 1: t = silu(pre), store tf32 to Ts -------
        const int j = jb + jl;
        const float dx0 = xi0 - x[j * 3 + 0];
        const float dx1 = xi1 - x[j * 3 + 1];
        const float dx2 = xi2 - x[j * 3 + 2];
        const float d2  = dx0 * dx0 + dx1 * dx1 + dx2 * dx2;
        const float aij = arow[j];
        const float4* pjr = (const float4*)(g_Pj + j * 64);
        const float* pir  = Pi_s + (il_e << 6);
        uint4* trow = (uint4*)(Ts + tid * 68);
#pragma unroll
        for (int k4 = 0; k4 < 16; k4++) {
            float4 pj = pjr[k4];
            int k = k4 * 4;
            float p0 = pir[k]     + pj.x + d2 * wds[k]     + aij * was[k];
            float p1 = pir[k + 1] + pj.y + d2 * wds[k + 1] + aij * was[k + 1];
            float p2 = pir[k + 2] + pj.z + d2 * wds[k + 2] + aij * was[k + 2];
            float p3 = pir[k + 3] + pj.w + d2 * wds[k + 3] + aij * was[k + 3];
            float v0, v1, v2, v3;
            silu2(p0, p1, v0, v1);
            silu2(p2, p3, v2, v3);
            uint4 v; v.x = f2tf(v0); v.y = f2tf(v1); v.z = f2tf(v2); v.w = f2tf(v3);
            trow[k4] = v;
        }
        __syncwarp();
        // ---------------- gemm1: m_pre = T @ We2 + be2 -------------------
        float acc[2][8][4];
        do_gemm(Ts, Wt2, be2s, acc, wrow, g, t4);
        __syncwarp();
        // ---------------- epilogue1: m = silu; macc; Ts <- tf32(m) -------
#pragma unroll
        for (int mt = 0; mt < 2; mt++) {
            const int e0 = wrow + mt * 16 + g;
            const int e1 = e0 + 8;
            const bool d0 = (jb + (e0 & 127)) == igw;  // diagonal row?
            const bool d1 = (jb + (e1 & 127)) == igw;
#pragma unroll
            for (int nt = 0; nt < 8; nt++) {
                float m0, m1, m2, m3;
                silu2(acc[mt][nt][0], acc[mt][nt][1], m0, m1);
                silu2(acc[mt][nt][2], acc[mt][nt][3], m2, m3);
                if (!d0) { macc[nt * 2] += m0; macc[nt * 2 + 1] += m1; }
                if (!d1) { macc[nt * 2] += m2; macc[nt * 2 + 1] += m3; }
                uint32_t* rp0 = Ts + e0 * 68 + nt * 8 + t4 * 2;
                uint32_t* rp1 = Ts + e1 * 68 + nt * 8 + t4 * 2;
                rp0[0] = f2tf(m0); rp0[1] = f2tf(m1);
                rp1[0] = f2tf(m2); rp1[1] = f2tf(m3);
            }
        }
        __syncwarp();
        // ---------------- gemm2: u_pre = M @ Wx1 + bx1 -------------------
        do_gemm(Ts, Wt1, bx1s, acc, wrow, g, t4);
        // ---------------- epilogue2: s = silu(u) . Wx2 + bx2 -------------
        float sp0 = 0.f, sp1 = 0.f, sp2 = 0.f, sp3 = 0.f;
#pragma unroll
        for (int mt = 0; mt < 2; mt++) {
#pragma unroll
            for (int nt = 0; nt < 8; nt++) {
                float u0, u1, u2, u3;
                silu2(acc[mt][nt][0], acc[mt][nt][1], u0, u1);
                silu2(acc[mt][nt][2], acc[mt][nt][3], u2, u3);
                float w0 = wx2s[nt * 8 + t4 * 2];
                float w1 = wx2s[nt * 8 + t4 * 2 + 1];
                float lo = u0 * w0 + u1 * w1;
                float hi = u2 * w0 + u3 * w1;
                if (mt == 0) { sp0 += lo; sp1 += hi; }
                else         { sp2 += lo; sp3 += hi; }
            }
        }
        sp0 += __shfl_xor_sync(0xffffffffu, sp0, 1);
        sp0 += __shfl_xor_sync(0xffffffffu, sp0, 2);
        sp1 += __shfl_xor_sync(0xffffffffu, sp1, 1);
        sp1 += __shfl_xor_sync(0xffffffffu, sp1, 2);
        sp2 += __shfl_xor_sync(0xffffffffu, sp2, 1);
        sp2 += __shfl_xor_sync(0xffffffffu, sp2, 2);
        sp3 += __shfl_xor_sync(0xffffffffu, sp3, 1);
        sp3 += __shfl_xor_sync(0xffffffffu, sp3, 2);
        if (t4 == 0) {
            s_sh[wrow + g]      = sp0 + bx2v;
            s_sh[wrow + g + 8]  = sp1 + bx2v;
            s_sh[wrow + 16 + g] = sp2 + bx2v;
            s_sh[wrow + 24 + g] = sp3 + bx2v;
        }
        __syncwarp();
        // ---------------- phase 4: coordinate accumulation ---------------
        float s = s_sh[tid];
        if (j != ig_e) {
            xa0 = fmaf(dx0, s, xa0);
            xa1 = fmaf(dx1, s, xa1);
            xa2 = fmaf(dx2, s, xa2);
        }
    }

    // ---- macc: sum over the 8 g-groups (rows) within each warp ----------
#pragma unroll
    for (int q = 0; q < 16; q++) {
        macc[q] += __shfl_xor_sync(0xffffffffu, macc[q], 4);
        macc[q] += __shfl_xor_sync(0xffffffffu, macc[q], 8);
        macc[q] += __shfl_xor_sync(0xffffffffu, macc[q], 16);
    }
    if (lane < 4) {
#pragma unroll
        for (int nt = 0; nt < 8; nt++) {
            mired[warp * 64 + nt * 8 + lane * 2]     = macc[nt * 2];
            mired[warp * 64 + nt * 8 + lane * 2 + 1] = macc[nt * 2 + 1];
        }
    }
    // ---- coordinate: full warp reduce (all lanes share the same i) ------
#pragma unroll
    for (int o = 16; o >= 1; o >>= 1) {
        xa0 += __shfl_xor_sync(0xffffffffu, xa0, o);
        xa1 += __shfl_xor_sync(0xffffffffu, xa1, o);
        xa2 += __shfl_xor_sync(0xffffffffu, xa2, o);
    }
    if (lane == 0) {
        xred[warp * 3 + 0] = xa0;
        xred[warp * 3 + 1] = xa1;
        xred[warp * 3 + 2] = xa2;
    }
    __syncthreads();

    if (tid < 128) {  // m_i = sum over the 4 warps of each i-row
        int il = tid >> 6, c = tid & 63;
        mi_s[tid] = mired[(il * 4 + 0) * 64 + c] + mired[(il * 4 + 1) * 64 + c] +
                    mired[(il * 4 + 2) * 64 + c] + mired[(il * 4 + 3) * 64 + c];
    }
    if (tid < 6) {    // x_new
        int il = tid / 3, d = tid - il * 3;
        float ssum = xred[il * 12 + d] + xred[il * 12 + 3 + d] +
                     xred[il * 12 + 6 + d] + xred[il * 12 + 9 + d];
        out[(ibase + il) * 3 + d] =
            fmaf(1.f / (float)(M_NODES - 1), ssum, x[(ibase + il) * 3 + d]);
    }
    __syncthreads();

    if (tid < 128) {  // h hidden layer
        int il = tid >> 6, c = tid & 63, ig = ibase + il;
        float a1 = bh1[c];
        const float* hr = h + ig * 64;
#pragma unroll 8
        for (int k = 0; k < 64; k++) a1 = fmaf(hr[k], Wh1[k * 64 + c], a1);
        const float* mr = mi_s + il * 64;
#pragma unroll 8
        for (int k = 0; k < 64; k++) a1 = fmaf(mr[k], Wh1[(64 + k) * 64 + c], a1);
        hids[tid] = silu1(a1);
    }
    __syncthreads();
    if (tid < 128) {  // h output layer
        int il = tid >> 6, c = tid & 63;
        float a2 = bh2[c];
        const float* hp = hids + il * 64;
#pragma unroll 8
        for (int k = 0; k < 64; k++) a2 = fmaf(hp[k], Wh2[k * 64 + c], a2);
        out[3 * M_NODES + (ibase + il) * 64 + c] = a2;
    }
}

extern "C" void kernel_launch(void* const* d_in, const int* in_sizes, int n_in,
                              void* d_out, int out_size) {
    const float* x   = (const float*)d_in[0];
    const float* a   = (const float*)d_in[1];
    const float* h   = (const float*)d_in[2];
    const float* We1 = (const float*)d_in[3];
    const float* be1 = (const float*)d_in[4];
    const float* We2 = (const float*)d_in[5];
    const float* be2 = (const float*)d_in[6];
    const float* Wx1 = (const float*)d_in[7];
    const float* bx1 = (const float*)d_in[8];
    const float* Wx2 = (const float*)d_in[9];
    const float* bx2 = (const float*)d_in[10];
    const float* Wh1 = (const float*)d_in[11];
    const float* bh1 = (const float*)d_in[12];
    const float* Wh2 = (const float*)d_in[13];
    const float* bh2 = (const float*)d_in[14];
    float* out = (float*)d_out;

    cudaFuncSetAttribute(ecnn_main, cudaFuncAttributeMaxDynamicSharedMemorySize,
                         SMEM_BYTES);

    prep_kernel<<<(M_NODES * 64) / NTH, NTH>>>(h, We1, be1);
    ecnn_main<<<M_NODES / BI, NTH, SMEM_BYTES>>>(
        x, a, h, We1, We2, be2, Wx1, bx1, Wx2, bx2, Wh1, bh1, Wh2, bh2, out);
}

// round 3
// speedup vs baseline: 3.1239x; 1.3539x over previous
#include <cuda_runtime.h>
#include <cstdint>

#define M_NODES 1024
#define NTH 256
#define TJ 256
#define NBLK 148
#define TSTRIDE 68

// scratch (no cudaMalloc allowed)
__device__ float g_Pi[M_NODES * 64];
__device__ float g_Pj[M_NODES * 64];

__device__ __forceinline__ uint32_t f2tf(float f) {
    uint32_t r; asm("cvt.rna.tf32.f32 %0, %1;" : "=r"(r) : "f"(f)); return r;
}
// silu(x) = x*sigmoid(x) = 0.5x*(1+tanh(x/2)) : exactly 1 MUFU + 2 FMA-class ops
__device__ __forceinline__ float silu_t(float v) {
    float hx = 0.5f * v;
    float t;
    asm("tanh.approx.f32 %0, %1;" : "=f"(t) : "f"(hx));
    return fmaf(hx, t, hx);
}

__device__ __forceinline__ void mma8(float* c, const uint32_t* a, const uint32_t* b) {
    asm volatile(
        "mma.sync.aligned.m16n8k8.row.col.f32.tf32.tf32.f32 "
        "{%0,%1,%2,%3}, {%4,%5,%6,%7}, {%8,%9}, {%0,%1,%2,%3};"
        : "+f"(c[0]), "+f"(c[1]), "+f"(c[2]), "+f"(c[3])
        : "r"(a[0]), "r"(a[1]), "r"(a[2]), "r"(a[3]), "r"(b[0]), "r"(b[1]));
}

// ---------------------------------------------------------------------------
__global__ void prep_kernel(const float* __restrict__ h,
                            const float* __restrict__ We1,
                            const float* __restrict__ be1) {
    int idx = blockIdx.x * blockDim.x + threadIdx.x;
    int i = idx >> 6, c = idx & 63;
    const float* hr = h + i * 64;
    float pi = be1[c], pj = 0.f;
#pragma unroll 16
    for (int k = 0; k < 64; k++) {
        float hv = hr[k];
        pi = fmaf(hv, We1[k * 64 + c], pi);
        pj = fmaf(hv, We1[(64 + k) * 64 + c], pj);
    }
    g_Pi[idx] = pi;
    g_Pj[idx] = pj;
}

// ---------------------------------------------------------------------------
// Warp-GEMM: A = own 32 rows of Ts (tf32, natural cols, stride 68);
// B from fragment-ordered weight array Wf:
//   Wf word index = ((kt*4+np)*32 + lane)*4 + (nt&1)*2 + hi
// holding Wt[n][k] = W[k][n] with n = nt*8+g, k = kt*8+t4+4*hi, np = nt>>1.
// bias in fragment order biasf[t4*16 + nt*2 + s].
// ---------------------------------------------------------------------------
__device__ __forceinline__ void do_gemm(const uint32_t* __restrict__ Ts,
                                        const uint32_t* __restrict__ Wf,
                                        const float* __restrict__ biasf,
                                        float acc[2][8][4],
                                        int wrow, int g, int t4, int lane) {
    const float4* bf = (const float4*)(biasf + t4 * 16);
#pragma unroll
    for (int np = 0; np < 4; np++) {
        float4 b = bf[np];
#pragma unroll
        for (int mt = 0; mt < 2; mt++) {
            acc[mt][2*np][0] = b.x; acc[mt][2*np][1] = b.y;
            acc[mt][2*np][2] = b.x; acc[mt][2*np][3] = b.y;
            acc[mt][2*np+1][0] = b.z; acc[mt][2*np+1][1] = b.w;
            acc[mt][2*np+1][2] = b.z; acc[mt][2*np+1][3] = b.w;
        }
    }
#pragma unroll
    for (int kt = 0; kt < 8; kt++) {
        const int kc = kt * 8 + t4;
        uint32_t A[2][4];
#pragma unroll
        for (int mt = 0; mt < 2; mt++) {
            const uint32_t* r0 = Ts + (wrow + mt * 16 + g) * TSTRIDE;
            A[mt][0] = r0[kc];
            A[mt][1] = r0[8 * TSTRIDE + kc];
            A[mt][2] = r0[kc + 4];
            A[mt][3] = r0[8 * TSTRIDE + kc + 4];
        }
#pragma unroll
        for (int np = 0; np < 4; np++) {
            uint4 Bv = ((const uint4*)Wf)[(kt * 4 + np) * 32 + lane];
            uint32_t B0[2] = {Bv.x, Bv.y};
            uint32_t B1[2] = {Bv.z, Bv.w};
            mma8(acc[0][2*np],     A[0], B0);
            mma8(acc[1][2*np],     A[1], B0);
            mma8(acc[0][2*np+1],   A[0], B1);
            mma8(acc[1][2*np+1],   A[1], B1);
        }
    }
}

// ---------------------------------------------------------------------------
// Persistent fused kernel: 148 CTAs, each loops i = bid, bid+148, ...
// Per i: one 256-edge j-tile x 4 iterations; warp w owns tile rows [32w,32w+32).
// ---------------------------------------------------------------------------
// SMEM (u32 words):
// Ts 17408 | Wf2 4096 | Wf1 4096 | Wh1s 8192 | Wh2s 4096 | xs 3072 |
// biasf2 64 | biasf1 64 | wx2f 64 | wdwa 128 | Pi_s 64 | s_sh 256 |
// mired 512 | mi_s 64 | hids 64 | xred 24   = 42264 words
#define SMEM_BYTES (42264 * 4)

__global__ void __launch_bounds__(NTH, 1)
ecnn_main(const float* __restrict__ x, const float* __restrict__ a,
          const float* __restrict__ h, const float* __restrict__ We1,
          const float* __restrict__ We2, const float* __restrict__ be2,
          const float* __restrict__ Wx1, const float* __restrict__ bx1,
          const float* __restrict__ Wx2, const float* __restrict__ bx2,
          const float* __restrict__ Wh1, const float* __restrict__ bh1,
          const float* __restrict__ Wh2, const float* __restrict__ bh2,
          float* __restrict__ out) {
    extern __shared__ uint32_t sm[];
    uint32_t* Ts   = sm;
    uint32_t* Wf2  = sm + 17408;
    uint32_t* Wf1  = sm + 21504;
    float* Wh1s    = (float*)(sm + 25600);
    float* Wh2s    = (float*)(sm + 33792);
    float* xs      = (float*)(sm + 37888);
    float* fmisc   = (float*)(sm + 40960);
    float* biasf2  = fmisc;         // 64
    float* biasf1  = fmisc + 64;    // 64
    float* wx2f    = fmisc + 128;   // 64
    float* wdwa    = fmisc + 192;   // 128
    float* Pi_s    = fmisc + 320;   // 64
    float* s_sh    = fmisc + 384;   // 256
    float* mired   = fmisc + 640;   // 512
    float* mi_s    = fmisc + 1152;  // 64
    float* hids    = fmisc + 1216;  // 64
    float* xred    = fmisc + 1280;  // 24

    const int tid  = threadIdx.x;
    const int lane = tid & 31;
    const int warp = tid >> 5;
    const int wrow = warp << 5;
    const int g    = lane >> 2;
    const int t4   = lane & 3;

    // ---- one-time staging (persistent CTA) ----
    for (int idx = tid; idx < 4096; idx += NTH) {
        int k = idx >> 6, n = idx & 63;
        int gg = n & 7, nt = n >> 3, tt = k & 3, hi = (k >> 2) & 1, kt = k >> 3;
        int dst = ((kt * 4 + (nt >> 1)) * 32 + (gg * 4 + tt)) * 4 + (nt & 1) * 2 + hi;
        Wf2[dst] = f2tf(We2[idx]);
        Wf1[dst] = f2tf(Wx1[idx]);
    }
    for (int idx = tid; idx < 8192; idx += NTH) Wh1s[idx] = Wh1[idx];
    for (int idx = tid; idx < 4096; idx += NTH) Wh2s[idx] = Wh2[idx];
    for (int idx = tid; idx < 3072; idx += NTH) xs[idx] = x[idx];
    if (tid < 64) {
        int nt = tid >> 3, u = tid & 7;
        int dst = (u >> 1) * 16 + nt * 2 + (u & 1);
        biasf2[dst] = be2[tid];
        biasf1[dst] = bx1[tid];
        wx2f[dst]   = Wx2[tid];
        wdwa[(tid >> 2) * 8 + (tid & 3)]     = We1[128 * 64 + tid];
        wdwa[(tid >> 2) * 8 + 4 + (tid & 3)] = We1[129 * 64 + tid];
    }
    __syncthreads();

    const float bx2v = bx2[0];
    const float C = 1.0f / (float)(M_NODES - 1);

    for (int i = blockIdx.x; i < M_NODES; i += NBLK) {
        __syncthreads();   // s_sh/Pi_s/mired reuse from previous i
        if (tid < 64) Pi_s[tid] = g_Pi[i * 64 + tid];
        __syncthreads();

        const float xi0 = xs[i * 3 + 0];
        const float xi1 = xs[i * 3 + 1];
        const float xi2 = xs[i * 3 + 2];
        const float* arow = a + (size_t)i * M_NODES;

        float macc[16];
#pragma unroll
        for (int q = 0; q < 16; q++) macc[q] = 0.f;
        float xa0 = 0.f, xa1 = 0.f, xa2 = 0.f;

        for (int jb = 0; jb < M_NODES; jb += TJ) {
            __syncwarp();   // Ts/s_sh reuse (warp-local rows)
            const int j = jb + tid;
            const float dx0 = xi0 - xs[j * 3 + 0];
            const float dx1 = xi1 - xs[j * 3 + 1];
            const float dx2 = xi2 - xs[j * 3 + 2];
            const float d2  = dx0 * dx0 + dx1 * dx1 + dx2 * dx2;
            const float aij = arow[j];

            // ---- phase 1: t = silu(pre) -> Ts (tf32, natural cols) ----
            const float4* pjr = (const float4*)(g_Pj + j * 64);
            uint4* trow = (uint4*)(Ts + tid * TSTRIDE);
#pragma unroll
            for (int k4 = 0; k4 < 16; k4++) {
                float4 pj = pjr[k4];
                float4 pi = *(const float4*)&Pi_s[k4 * 4];
                float4 wd = *(const float4*)&wdwa[k4 * 8];
                float4 wa = *(const float4*)&wdwa[k4 * 8 + 4];
                float p0 = fmaf(aij, wa.x, fmaf(d2, wd.x, pi.x + pj.x));
                float p1 = fmaf(aij, wa.y, fmaf(d2, wd.y, pi.y + pj.y));
                float p2 = fmaf(aij, wa.z, fmaf(d2, wd.z, pi.z + pj.z));
                float p3 = fmaf(aij, wa.w, fmaf(d2, wd.w, pi.w + pj.w));
                uint4 v;
                v.x = f2tf(silu_t(p0));
                v.y = f2tf(silu_t(p1));
                v.z = f2tf(silu_t(p2));
                v.w = f2tf(silu_t(p3));
                trow[k4] = v;
            }
            __syncwarp();

            // ---- gemm1: m_pre = T @ We2 + be2 ----
            float acc[2][8][4];
            do_gemm(Ts, Wf2, biasf2, acc, wrow, g, t4, lane);
            __syncwarp();

            // ---- epilogue1: m = silu; macc; Ts <- tf32(m) ----
#pragma unroll
            for (int mt = 0; mt < 2; mt++) {
                const int e0 = wrow + mt * 16 + g;
                const int e1 = e0 + 8;
                const bool d0 = (jb + e0) == i;
                const bool d1 = (jb + e1) == i;
#pragma unroll
                for (int nt = 0; nt < 8; nt++) {
                    float m0 = silu_t(acc[mt][nt][0]);
                    float m1 = silu_t(acc[mt][nt][1]);
                    float m2 = silu_t(acc[mt][nt][2]);
                    float m3 = silu_t(acc[mt][nt][3]);
                    if (!d0) { macc[nt*2] += m0; macc[nt*2+1] += m1; }
                    if (!d1) { macc[nt*2] += m2; macc[nt*2+1] += m3; }
                    uint2 v0; v0.x = f2tf(m0); v0.y = f2tf(m1);
                    uint2 v1; v1.x = f2tf(m2); v1.y = f2tf(m3);
                    *(uint2*)&Ts[e0 * TSTRIDE + nt * 8 + t4 * 2] = v0;
                    *(uint2*)&Ts[e1 * TSTRIDE + nt * 8 + t4 * 2] = v1;
                }
            }
            __syncwarp();

            // ---- gemm2: u_pre = M @ Wx1 + bx1 ----
            do_gemm(Ts, Wf1, biasf1, acc, wrow, g, t4, lane);

            // ---- epilogue2: s = silu(u) . Wx2 + bx2 ----
            const float4* wxf = (const float4*)(wx2f + t4 * 16);
            float sp0 = 0.f, sp1 = 0.f, sp2 = 0.f, sp3 = 0.f;
#pragma unroll
            for (int np = 0; np < 4; np++) {
                float4 w = wxf[np];
#pragma unroll
                for (int mt = 0; mt < 2; mt++) {
                    float u0 = silu_t(acc[mt][2*np][0]);
                    float u1 = silu_t(acc[mt][2*np][1]);
                    float u2 = silu_t(acc[mt][2*np][2]);
                    float u3 = silu_t(acc[mt][2*np][3]);
                    float lo = fmaf(u0, w.x, u1 * w.y);
                    float hi = fmaf(u2, w.x, u3 * w.y);
                    float u4 = silu_t(acc[mt][2*np+1][0]);
                    float u5 = silu_t(acc[mt][2*np+1][1]);
                    float u6 = silu_t(acc[mt][2*np+1][2]);
                    float u7 = silu_t(acc[mt][2*np+1][3]);
                    lo = fmaf(u4, w.z, fmaf(u5, w.w, lo));
                    hi = fmaf(u6, w.z, fmaf(u7, w.w, hi));
                    if (mt == 0) { sp0 += lo; sp1 += hi; }
                    else         { sp2 += lo; sp3 += hi; }
                }
            }
            sp0 += __shfl_xor_sync(0xffffffffu, sp0, 1);
            sp0 += __shfl_xor_sync(0xffffffffu, sp0, 2);
            sp1 += __shfl_xor_sync(0xffffffffu, sp1, 1);
            sp1 += __shfl_xor_sync(0xffffffffu, sp1, 2);
            sp2 += __shfl_xor_sync(0xffffffffu, sp2, 1);
            sp2 += __shfl_xor_sync(0xffffffffu, sp2, 2);
            sp3 += __shfl_xor_sync(0xffffffffu, sp3, 1);
            sp3 += __shfl_xor_sync(0xffffffffu, sp3, 2);
            if (t4 == 0) {
                s_sh[wrow + g]      = sp0 + bx2v;
                s_sh[wrow + 8 + g]  = sp1 + bx2v;
                s_sh[wrow + 16 + g] = sp2 + bx2v;
                s_sh[wrow + 24 + g] = sp3 + bx2v;
            }
            __syncwarp();

            // ---- phase 4: coordinate accumulation ----
            float s = s_sh[tid];
            if (j != i) {
                xa0 = fmaf(dx0, s, xa0);
                xa1 = fmaf(dx1, s, xa1);
                xa2 = fmaf(dx2, s, xa2);
            }
        }

        // ---- macc: reduce over g within warp, write per-warp partials ----
#pragma unroll
        for (int q = 0; q < 16; q++) {
            macc[q] += __shfl_xor_sync(0xffffffffu, macc[q], 4);
            macc[q] += __shfl_xor_sync(0xffffffffu, macc[q], 8);
            macc[q] += __shfl_xor_sync(0xffffffffu, macc[q], 16);
        }
        if (lane < 4) {
#pragma unroll
            for (int nt = 0; nt < 8; nt++) {
                mired[warp * 64 + nt * 8 + lane * 2]     = macc[nt * 2];
                mired[warp * 64 + nt * 8 + lane * 2 + 1] = macc[nt * 2 + 1];
            }
        }
#pragma unroll
        for (int o = 16; o >= 1; o >>= 1) {
            xa0 += __shfl_xor_sync(0xffffffffu, xa0, o);
            xa1 += __shfl_xor_sync(0xffffffffu, xa1, o);
            xa2 += __shfl_xor_sync(0xffffffffu, xa2, o);
        }
        if (lane == 0) {
            xred[warp * 3 + 0] = xa0;
            xred[warp * 3 + 1] = xa1;
            xred[warp * 3 + 2] = xa2;
        }
        __syncthreads();

        if (tid < 64) {
            float s = 0.f;
#pragma unroll
            for (int w = 0; w < 8; w++) s += mired[w * 64 + tid];
            mi_s[tid] = s;
        }
        if (tid < 3) {
            float s = 0.f;
#pragma unroll
            for (int w = 0; w < 8; w++) s += xred[w * 3 + tid];
            out[i * 3 + tid] = fmaf(C, s, xs[i * 3 + tid]);
        }
        __syncthreads();

        // ---- h_new: 2-layer MLP, k-split across 4 thread groups ----
        {
            const int c = tid & 63, p = tid >> 6;
            float a1 = 0.f;
            if (p < 2) {
                const float* hr = h + i * 64 + p * 32;
                const float* wr = Wh1s + (p * 32) * 64 + c;
#pragma unroll 8
                for (int q = 0; q < 32; q++) a1 = fmaf(hr[q], wr[q * 64], a1);
            } else {
                const float* mr = mi_s + (p - 2) * 32;
                const float* wr = Wh1s + (64 + (p - 2) * 32) * 64 + c;
#pragma unroll 8
                for (int q = 0; q < 32; q++) a1 = fmaf(mr[q], wr[q * 64], a1);
            }
            s_sh[tid] = a1;
        }
        __syncthreads();
        if (tid < 64)
            hids[tid] = silu_t(bh1[tid] + s_sh[tid] + s_sh[64 + tid] +
                               s_sh[128 + tid] + s_sh[192 + tid]);
        __syncthreads();
        {
            const int c = tid & 63, p = tid >> 6;
            float a2 = 0.f;
            const float* hp = hids + p * 16;
            const float* wr = Wh2s + (p * 16) * 64 + c;
#pragma unroll 8
            for (int q = 0; q < 16; q++) a2 = fmaf(hp[q], wr[q * 64], a2);
            s_sh[tid] = a2;
        }
        __syncthreads();
        if (tid < 64)
            out[3 * M_NODES + i * 64 + tid] =
                bh2[tid] + s_sh[tid] + s_sh[64 + tid] + s_sh[128 + tid] + s_sh[192 + tid];
    }
}

extern "C" void kernel_launch(void* const* d_in, const int* in_sizes, int n_in,
                              void* d_out, int out_size) {
    const float* x   = (const float*)d_in[0];
    const float* a   = (const float*)d_in[1];
    const float* h   = (const float*)d_in[2];
    const float* We1 = (const float*)d_in[3];
    const float* be1 = (const float*)d_in[4];
    const float* We2 = (const float*)d_in[5];
    const float* be2 = (const float*)d_in[6];
    const float* Wx1 = (const float*)d_in[7];
    const float* bx1 = (const float*)d_in[8];
    const float* Wx2 = (const float*)d_in[9];
    const float* bx2 = (const float*)d_in[10];
    const float* Wh1 = (const float*)d_in[11];
    const float* bh1 = (const float*)d_in[12];
    const float* Wh2 = (const float*)d_in[13];
    const float* bh2 = (const float*)d_in[14];
    float* out = (float*)d_out;

    cudaFuncSetAttribute(ecnn_main, cudaFuncAttributeMaxDynamicSharedMemorySize,
                         SMEM_BYTES);

    prep_kernel<<<(M_NODES * 64) / NTH, NTH>>>(h, We1, be1);
    ecnn_main<<<NBLK, NTH, SMEM_BYTES>>>(
        x, a, h, We1, We2, be2, Wx1, bx1, Wx2, bx2, Wh1, bh1, Wh2, bh2, out);
}

// round 4
// speedup vs baseline: 3.3428x; 1.0701x over previous
#include <cuda_runtime.h>
#include <cstdint>

#define M_NODES 1024
#define NTH 512
#define TJ 512
#define NBLK 148
#define TSTRIDE 68

// scratch (no cudaMalloc allowed)
__device__ float g_Pi[M_NODES * 64];
__device__ float g_Pj[M_NODES * 64];

__device__ __forceinline__ uint32_t f2tf(float f) {
    uint32_t r; asm("cvt.rna.tf32.f32 %0, %1;" : "=r"(r) : "f"(f)); return r;
}
// silu(x) = x*sigmoid(x) = 0.5x*(1+tanh(x/2)) : exactly 1 MUFU + 2 FMA-class ops
__device__ __forceinline__ float silu_t(float v) {
    float hx = 0.5f * v;
    float t;
    asm("tanh.approx.f32 %0, %1;" : "=f"(t) : "f"(hx));
    return fmaf(hx, t, hx);
}

__device__ __forceinline__ void mma8(float* c, const uint32_t* a, const uint32_t* b) {
    asm volatile(
        "mma.sync.aligned.m16n8k8.row.col.f32.tf32.tf32.f32 "
        "{%0,%1,%2,%3}, {%4,%5,%6,%7}, {%8,%9}, {%0,%1,%2,%3};"
        : "+f"(c[0]), "+f"(c[1]), "+f"(c[2]), "+f"(c[3])
        : "r"(a[0]), "r"(a[1]), "r"(a[2]), "r"(a[3]), "r"(b[0]), "r"(b[1]));
}

// ---------------------------------------------------------------------------
__global__ void prep_kernel(const float* __restrict__ h,
                            const float* __restrict__ We1,
                            const float* __restrict__ be1) {
    int idx = blockIdx.x * blockDim.x + threadIdx.x;
    int i = idx >> 6, c = idx & 63;
    const float* hr = h + i * 64;
    float pi = be1[c], pj = 0.f;
#pragma unroll 16
    for (int k = 0; k < 64; k++) {
        float hv = hr[k];
        pi = fmaf(hv, We1[k * 64 + c], pi);
        pj = fmaf(hv, We1[(64 + k) * 64 + c], pj);
    }
    g_Pi[idx] = pi;
    g_Pj[idx] = pj;
}

// ---------------------------------------------------------------------------
// Warp-GEMM: A = own 32 rows of Ts (tf32, natural cols, stride 68);
// B from fragment-ordered weight array Wf:
//   Wf word index = ((kt*4+np)*32 + lane)*4 + (nt&1)*2 + hi
// bias in fragment order biasf[t4*16 + nt*2 + s].
// ---------------------------------------------------------------------------
__device__ __forceinline__ void do_gemm(const uint32_t* __restrict__ Ts,
                                        const uint32_t* __restrict__ Wf,
                                        const float* __restrict__ biasf,
                                        float acc[2][8][4],
                                        int wrow, int g, int t4, int lane) {
    const float4* bf = (const float4*)(biasf + t4 * 16);
#pragma unroll
    for (int np = 0; np < 4; np++) {
        float4 b = bf[np];
#pragma unroll
        for (int mt = 0; mt < 2; mt++) {
            acc[mt][2*np][0] = b.x; acc[mt][2*np][1] = b.y;
            acc[mt][2*np][2] = b.x; acc[mt][2*np][3] = b.y;
            acc[mt][2*np+1][0] = b.z; acc[mt][2*np+1][1] = b.w;
            acc[mt][2*np+1][2] = b.z; acc[mt][2*np+1][3] = b.w;
        }
    }
#pragma unroll
    for (int kt = 0; kt < 8; kt++) {
        const int kc = kt * 8 + t4;
        uint32_t A[2][4];
#pragma unroll
        for (int mt = 0; mt < 2; mt++) {
            const uint32_t* r0 = Ts + (wrow + mt * 16 + g) * TSTRIDE;
            A[mt][0] = r0[kc];
            A[mt][1] = r0[8 * TSTRIDE + kc];
            A[mt][2] = r0[kc + 4];
            A[mt][3] = r0[8 * TSTRIDE + kc + 4];
        }
#pragma unroll
        for (int np = 0; np < 4; np++) {
            uint4 Bv = ((const uint4*)Wf)[(kt * 4 + np) * 32 + lane];
            uint32_t B0[2] = {Bv.x, Bv.y};
            uint32_t B1[2] = {Bv.z, Bv.w};
            mma8(acc[0][2*np],     A[0], B0);
            mma8(acc[1][2*np],     A[1], B0);
            mma8(acc[0][2*np+1],   A[0], B1);
            mma8(acc[1][2*np+1],   A[1], B1);
        }
    }
}

// ---------------------------------------------------------------------------
// Persistent fused kernel: 148 CTAs x 512 threads (16 warps).
// Per i: j-tile of 512 -> 2 iterations; warp w owns tile rows [32w, 32w+32):
// the entire j-loop is warp-synchronous (zero __syncthreads inside).
// ---------------------------------------------------------------------------
// SMEM (u32 words):
// Ts 512*68=34816 | Wf2 4096 | Wf1 4096 | xs 3072 | fmisc 2160 = 48240 words
#define SMEM_BYTES (48240 * 4)

__global__ void __launch_bounds__(NTH, 1)
ecnn_main(const float* __restrict__ x, const float* __restrict__ a,
          const float* __restrict__ h, const float* __restrict__ We1,
          const float* __restrict__ We2, const float* __restrict__ be2,
          const float* __restrict__ Wx1, const float* __restrict__ bx1,
          const float* __restrict__ Wx2, const float* __restrict__ bx2,
          const float* __restrict__ Wh1, const float* __restrict__ bh1,
          const float* __restrict__ Wh2, const float* __restrict__ bh2,
          float* __restrict__ out) {
    extern __shared__ uint32_t sm[];
    uint32_t* Ts   = sm;
    uint32_t* Wf2  = sm + 34816;
    uint32_t* Wf1  = sm + 38912;
    float* xs      = (float*)(sm + 43008);
    float* fmisc   = (float*)(sm + 46080);
    float* biasf2  = fmisc;         // 64
    float* biasf1  = fmisc + 64;    // 64
    float* wx2f    = fmisc + 128;   // 64
    float* wdwa    = fmisc + 192;   // 128
    float* Pi_s    = fmisc + 320;   // 64
    float* s_sh    = fmisc + 384;   // 512
    float* mired   = fmisc + 896;   // 16*64 = 1024
    float* mi_s    = fmisc + 1920;  // 64
    float* hids    = fmisc + 1984;  // 64
    float* xred    = fmisc + 2048;  // 48

    const int tid  = threadIdx.x;
    const int lane = tid & 31;
    const int warp = tid >> 5;
    const int wrow = warp << 5;
    const int g    = lane >> 2;
    const int t4   = lane & 3;

    // ---- one-time staging (persistent CTA) ----
    for (int idx = tid; idx < 4096; idx += NTH) {
        int k = idx >> 6, n = idx & 63;
        int gg = n & 7, nt = n >> 3, tt = k & 3, hi = (k >> 2) & 1, kt = k >> 3;
        int dst = ((kt * 4 + (nt >> 1)) * 32 + (gg * 4 + tt)) * 4 + (nt & 1) * 2 + hi;
        Wf2[dst] = f2tf(We2[idx]);
        Wf1[dst] = f2tf(Wx1[idx]);
    }
    for (int idx = tid; idx < 3072; idx += NTH) xs[idx] = x[idx];
    if (tid < 64) {
        int nt = tid >> 3, u = tid & 7;
        int dst = (u >> 1) * 16 + nt * 2 + (u & 1);
        biasf2[dst] = be2[tid];
        biasf1[dst] = bx1[tid];
        wx2f[dst]   = Wx2[tid];
        wdwa[(tid >> 2) * 8 + (tid & 3)]     = We1[128 * 64 + tid];
        wdwa[(tid >> 2) * 8 + 4 + (tid & 3)] = We1[129 * 64 + tid];
    }
    __syncthreads();

    const float bx2v = bx2[0];
    const float C = 1.0f / (float)(M_NODES - 1);

    for (int i = blockIdx.x; i < M_NODES; i += NBLK) {
        __syncthreads();   // s_sh/Pi_s/mired reuse from previous i
        if (tid < 64) Pi_s[tid] = g_Pi[i * 64 + tid];
        __syncthreads();

        const float xi0 = xs[i * 3 + 0];
        const float xi1 = xs[i * 3 + 1];
        const float xi2 = xs[i * 3 + 2];
        const float* arow = a + (size_t)i * M_NODES;

        float macc[16];
#pragma unroll
        for (int q = 0; q < 16; q++) macc[q] = 0.f;
        float xa0 = 0.f, xa1 = 0.f, xa2 = 0.f;

        for (int jb = 0; jb < M_NODES; jb += TJ) {
            __syncwarp();   // Ts/s_sh reuse (warp-local rows)
            const int j = jb + tid;
            const float dx0 = xi0 - xs[j * 3 + 0];
            const float dx1 = xi1 - xs[j * 3 + 1];
            const float dx2 = xi2 - xs[j * 3 + 2];
            const float d2  = dx0 * dx0 + dx1 * dx1 + dx2 * dx2;
            const float aij = arow[j];

            // ---- phase 1: t = silu(pre) -> Ts (tf32, natural cols) ----
            const float4* pjr = (const float4*)(g_Pj + j * 64);
            uint4* trow = (uint4*)(Ts + tid * TSTRIDE);
#pragma unroll
            for (int k4 = 0; k4 < 16; k4++) {
                float4 pj = pjr[k4];
                float4 pi = *(const float4*)&Pi_s[k4 * 4];
                float4 wd = *(const float4*)&wdwa[k4 * 8];
                float4 wa = *(const float4*)&wdwa[k4 * 8 + 4];
                float p0 = fmaf(aij, wa.x, fmaf(d2, wd.x, pi.x + pj.x));
                float p1 = fmaf(aij, wa.y, fmaf(d2, wd.y, pi.y + pj.y));
                float p2 = fmaf(aij, wa.z, fmaf(d2, wd.z, pi.z + pj.z));
                float p3 = fmaf(aij, wa.w, fmaf(d2, wd.w, pi.w + pj.w));
                uint4 v;
                v.x = f2tf(silu_t(p0));
                v.y = f2tf(silu_t(p1));
                v.z = f2tf(silu_t(p2));
                v.w = f2tf(silu_t(p3));
                trow[k4] = v;
            }
            __syncwarp();

            // ---- gemm1: m_pre = T @ We2 + be2 ----
            float acc[2][8][4];
            do_gemm(Ts, Wf2, biasf2, acc, wrow, g, t4, lane);
            __syncwarp();

            // ---- epilogue1: m = silu; macc; Ts <- tf32(m) ----
#pragma unroll
            for (int mt = 0; mt < 2; mt++) {
                const int e0 = wrow + mt * 16 + g;
                const int e1 = e0 + 8;
                const bool d0 = (jb + e0) == i;
                const bool d1 = (jb + e1) == i;
#pragma unroll
                for (int nt = 0; nt < 8; nt++) {
                    float m0 = silu_t(acc[mt][nt][0]);
                    float m1 = silu_t(acc[mt][nt][1]);
                    float m2 = silu_t(acc[mt][nt][2]);
                    float m3 = silu_t(acc[mt][nt][3]);
                    if (!d0) { macc[nt*2] += m0; macc[nt*2+1] += m1; }
                    if (!d1) { macc[nt*2] += m2; macc[nt*2+1] += m3; }
                    uint2 v0; v0.x = f2tf(m0); v0.y = f2tf(m1);
                    uint2 v1; v1.x = f2tf(m2); v1.y = f2tf(m3);
                    *(uint2*)&Ts[e0 * TSTRIDE + nt * 8 + t4 * 2] = v0;
                    *(uint2*)&Ts[e1 * TSTRIDE + nt * 8 + t4 * 2] = v1;
                }
            }
            __syncwarp();

            // ---- gemm2: u_pre = M @ Wx1 + bx1 ----
            do_gemm(Ts, Wf1, biasf1, acc, wrow, g, t4, lane);

            // ---- epilogue2: s = silu(u) . Wx2 + bx2 ----
            const float4* wxf = (const float4*)(wx2f + t4 * 16);
            float sp0 = 0.f, sp1 = 0.f, sp2 = 0.f, sp3 = 0.f;
#pragma unroll
            for (int np = 0; np < 4; np++) {
                float4 w = wxf[np];
#pragma unroll
                for (int mt = 0; mt < 2; mt++) {
                    float u0 = silu_t(acc[mt][2*np][0]);
                    float u1 = silu_t(acc[mt][2*np][1]);
                    float u2 = silu_t(acc[mt][2*np][2]);
                    float u3 = silu_t(acc[mt][2*np][3]);
                    float lo = fmaf(u0, w.x, u1 * w.y);
                    float hi = fmaf(u2, w.x, u3 * w.y);
                    float u4 = silu_t(acc[mt][2*np+1][0]);
                    float u5 = silu_t(acc[mt][2*np+1][1]);
                    float u6 = silu_t(acc[mt][2*np+1][2]);
                    float u7 = silu_t(acc[mt][2*np+1][3]);
                    lo = fmaf(u4, w.z, fmaf(u5, w.w, lo));
                    hi = fmaf(u6, w.z, fmaf(u7, w.w, hi));
                    if (mt == 0) { sp0 += lo; sp1 += hi; }
                    else         { sp2 += lo; sp3 += hi; }
                }
            }
            sp0 += __shfl_xor_sync(0xffffffffu, sp0, 1);
            sp0 += __shfl_xor_sync(0xffffffffu, sp0, 2);
            sp1 += __shfl_xor_sync(0xffffffffu, sp1, 1);
            sp1 += __shfl_xor_sync(0xffffffffu, sp1, 2);
            sp2 += __shfl_xor_sync(0xffffffffu, sp2, 1);
            sp2 += __shfl_xor_sync(0xffffffffu, sp2, 2);
            sp3 += __shfl_xor_sync(0xffffffffu, sp3, 1);
            sp3 += __shfl_xor_sync(0xffffffffu, sp3, 2);
            if (t4 == 0) {
                s_sh[wrow + g]      = sp0 + bx2v;
                s_sh[wrow + 8 + g]  = sp1 + bx2v;
                s_sh[wrow + 16 + g] = sp2 + bx2v;
                s_sh[wrow + 24 + g] = sp3 + bx2v;
            }
            __syncwarp();

            // ---- phase 4: coordinate accumulation ----
            float s = s_sh[tid];
            if (j != i) {
                xa0 = fmaf(dx0, s, xa0);
                xa1 = fmaf(dx1, s, xa1);
                xa2 = fmaf(dx2, s, xa2);
            }
        }

        // ---- macc: reduce over g within warp, write per-warp partials ----
#pragma unroll
        for (int q = 0; q < 16; q++) {
            macc[q] += __shfl_xor_sync(0xffffffffu, macc[q], 4);
            macc[q] += __shfl_xor_sync(0xffffffffu, macc[q], 8);
            macc[q] += __shfl_xor_sync(0xffffffffu, macc[q], 16);
        }
        if (lane < 4) {
#pragma unroll
            for (int nt = 0; nt < 8; nt++) {
                mired[warp * 64 + nt * 8 + lane * 2]     = macc[nt * 2];
                mired[warp * 64 + nt * 8 + lane * 2 + 1] = macc[nt * 2 + 1];
            }
        }
#pragma unroll
        for (int o = 16; o >= 1; o >>= 1) {
            xa0 += __shfl_xor_sync(0xffffffffu, xa0, o);
            xa1 += __shfl_xor_sync(0xffffffffu, xa1, o);
            xa2 += __shfl_xor_sync(0xffffffffu, xa2, o);
        }
        if (lane == 0) {
            xred[warp * 3 + 0] = xa0;
            xred[warp * 3 + 1] = xa1;
            xred[warp * 3 + 2] = xa2;
        }
        __syncthreads();

        if (tid < 64) {
            float s = 0.f;
#pragma unroll
            for (int w = 0; w < 16; w++) s += mired[w * 64 + tid];
            mi_s[tid] = s;
        }
        if (tid < 3) {
            float s = 0.f;
#pragma unroll
            for (int w = 0; w < 16; w++) s += xred[w * 3 + tid];
            out[i * 3 + tid] = fmaf(C, s, xs[i * 3 + tid]);
        }
        __syncthreads();

        // ---- h_new: 2-layer MLP (weights from L2; per-i cost is tiny) ----
        if (tid < 256) {
            const int c = tid & 63, p = tid >> 6;
            float a1 = 0.f;
            if (p < 2) {
                const float* hr = h + i * 64 + p * 32;
                const float* wr = Wh1 + (p * 32) * 64 + c;
#pragma unroll 8
                for (int q = 0; q < 32; q++) a1 = fmaf(hr[q], wr[q * 64], a1);
            } else {
                const float* mr = mi_s + (p - 2) * 32;
                const float* wr = Wh1 + (64 + (p - 2) * 32) * 64 + c;
#pragma unroll 8
                for (int q = 0; q < 32; q++) a1 = fmaf(mr[q], wr[q * 64], a1);
            }
            s_sh[tid] = a1;
        }
        __syncthreads();
        if (tid < 64)
            hids[tid] = silu_t(bh1[tid] + s_sh[tid] + s_sh[64 + tid] +
                               s_sh[128 + tid] + s_sh[192 + tid]);
        __syncthreads();
        if (tid < 256) {
            const int c = tid & 63, p = tid >> 6;
            float a2 = 0.f;
            const float* hp = hids + p * 16;
            const float* wr = Wh2 + (p * 16) * 64 + c;
#pragma unroll 8
            for (int q = 0; q < 16; q++) a2 = fmaf(hp[q], wr[q * 64], a2);
            s_sh[tid] = a2;
        }
        __syncthreads();
        if (tid < 64)
            out[3 * M_NODES + i * 64 + tid] =
                bh2[tid] + s_sh[tid] + s_sh[64 + tid] + s_sh[128 + tid] + s_sh[192 + tid];
    }
}

extern "C" void kernel_launch(void* const* d_in, const int* in_sizes, int n_in,
                              void* d_out, int out_size) {
    const float* x   = (const float*)d_in[0];
    const float* a   = (const float*)d_in[1];
    const float* h   = (const float*)d_in[2];
    const float* We1 = (const float*)d_in[3];
    const float* be1 = (const float*)d_in[4];
    const float* We2 = (const float*)d_in[5];
    const float* be2 = (const float*)d_in[6];
    const float* Wx1 = (const float*)d_in[7];
    const float* bx1 = (const float*)d_in[8];
    const float* Wx2 = (const float*)d_in[9];
    const float* bx2 = (const float*)d_in[10];
    const float* Wh1 = (const float*)d_in[11];
    const float* bh1 = (const float*)d_in[12];
    const float* Wh2 = (const float*)d_in[13];
    const float* bh2 = (const float*)d_in[14];
    float* out = (float*)d_out;

    cudaFuncSetAttribute(ecnn_main, cudaFuncAttributeMaxDynamicSharedMemorySize,
                         SMEM_BYTES);

    prep_kernel<<<(M_NODES * 64) / 256, 256>>>(h, We1, be1);
    ecnn_main<<<NBLK, NTH, SMEM_BYTES>>>(
        x, a, h, We1, We2, be2, Wx1, bx1, Wx2, bx2, Wh1, bh1, Wh2, bh2, out);
}

// round 6
// speedup vs baseline: 4.2844x; 1.2817x over previous
#include <cuda_runtime.h>
#include <cuda_fp16.h>
#include <cstdint>

#define M_NODES 1024
#define NTH 512
#define TJ 512
#define NBLK 148
#define TS36 36   // Ts row stride in u32 (32 data + 4 pad -> conflict-free)

// scratch (no cudaMalloc allowed)
__device__ float g_Pi[M_NODES * 64];
__device__ float g_Pj[M_NODES * 64];

__device__ __forceinline__ uint32_t h2(float lo, float hi) {
    __half2 t = __floats2half2_rn(lo, hi);
    return *(uint32_t*)&t;
}
// silu(x) = x*sigmoid(x) = 0.5x*(1+tanh(x/2)) : 1 MUFU + 2 FMA-class ops
__device__ __forceinline__ float silu_t(float v) {
    float hx = 0.5f * v;
    float t;
    asm("tanh.approx.f32 %0, %1;" : "=f"(t) : "f"(hx));
    return fmaf(hx, t, hx);
}

__device__ __forceinline__ void mma16(float* c, const uint32_t* a, const uint32_t* b) {
    asm volatile(
        "mma.sync.aligned.m16n8k16.row.col.f32.f16.f16.f32 "
        "{%0,%1,%2,%3}, {%4,%5,%6,%7}, {%8,%9}, {%0,%1,%2,%3};"
        : "+f"(c[0]), "+f"(c[1]), "+f"(c[2]), "+f"(c[3])
        : "r"(a[0]), "r"(a[1]), "r"(a[2]), "r"(a[3]), "r"(b[0]), "r"(b[1]));
}

// ---------------------------------------------------------------------------
__global__ void prep_kernel(const float* __restrict__ h,
                            const float* __restrict__ We1,
                            const float* __restrict__ be1) {
    int idx = blockIdx.x * blockDim.x + threadIdx.x;
    int i = idx >> 6, c = idx & 63;
    const float* hr = h + i * 64;
    float pi = be1[c], pj = 0.f;
#pragma unroll 16
    for (int k = 0; k < 64; k++) {
        float hv = hr[k];
        pi = fmaf(hv, We1[k * 64 + c], pi);
        pj = fmaf(hv, We1[(64 + k) * 64 + c], pj);
    }
    g_Pi[idx] = pi;
    g_Pj[idx] = pj;
}

// ---------------------------------------------------------------------------
// Warp-GEMM (fp16 m16n8k16): A = own 32 rows of Ts (halves, natural k order,
// row stride 36 u32); B from fragment-ordered half weights Wf:
//   u32 index = ((kt*4+np)*32 + lane)*4 + c,  c = sel2*2 + hi, half = k&1
//   holding  B[k][n] = W[k][n],  k = kt*16 + 2*t4 + (k&1) + 8*hi,
//                                n = np*16 + sel2*8 + g.
// bias in fragment order biasf[t4*16 + nt*2 + s]  (col = nt*8 + 2*t4 + s).
// ---------------------------------------------------------------------------
__device__ __forceinline__ void do_gemm(const uint32_t* __restrict__ Ts,
                                        const uint32_t* __restrict__ Wf,
                                        const float* __restrict__ biasf,
                                        float acc[2][8][4],
                                        int wrow, int g, int t4, int lane) {
    const float4* bf = (const float4*)(biasf + t4 * 16);
#pragma unroll
    for (int np = 0; np < 4; np++) {
        float4 b = bf[np];
#pragma unroll
        for (int mt = 0; mt < 2; mt++) {
            acc[mt][2*np][0] = b.x; acc[mt][2*np][1] = b.y;
            acc[mt][2*np][2] = b.x; acc[mt][2*np][3] = b.y;
            acc[mt][2*np+1][0] = b.z; acc[mt][2*np+1][1] = b.w;
            acc[mt][2*np+1][2] = b.z; acc[mt][2*np+1][3] = b.w;
        }
    }
#pragma unroll
    for (int kt = 0; kt < 4; kt++) {
        const int kc = kt * 8 + t4;
        uint32_t A[2][4];
#pragma unroll
        for (int mt = 0; mt < 2; mt++) {
            const uint32_t* r0 = Ts + (wrow + mt * 16 + g) * TS36;
            const uint32_t* r1 = r0 + 8 * TS36;
            A[mt][0] = r0[kc];
            A[mt][1] = r1[kc];
            A[mt][2] = r0[kc + 4];
            A[mt][3] = r1[kc + 4];
        }
#pragma unroll
        for (int np = 0; np < 4; np++) {
            uint4 Bv = ((const uint4*)Wf)[(kt * 4 + np) * 32 + lane];
            uint32_t B0[2] = {Bv.x, Bv.y};
            uint32_t B1[2] = {Bv.z, Bv.w};
            mma16(acc[0][2*np],   A[0], B0);
            mma16(acc[1][2*np],   A[1], B0);
            mma16(acc[0][2*np+1], A[0], B1);
            mma16(acc[1][2*np+1], A[1], B1);
        }
    }
}

// ---------------------------------------------------------------------------
// Persistent fused kernel: 148 CTAs x 512 threads (16 warps).
// Per i: j-tile of 512 -> 2 iterations; warp w owns tile rows [32w, 32w+32):
// the j-loop is fully warp-synchronous (zero __syncthreads inside).
// ---------------------------------------------------------------------------
// SMEM (u32 words):
// Ts 512*36=18432 | Wf2 2048 | Wf1 2048 | xs 3072 | fmisc 2160 = 27760 words
#define SMEM_BYTES (27760 * 4)

__global__ void __launch_bounds__(NTH, 1)
ecnn_main(const float* __restrict__ x, const float* __restrict__ a,
          const float* __restrict__ h, const float* __restrict__ We1,
          const float* __restrict__ We2, const float* __restrict__ be2,
          const float* __restrict__ Wx1, const float* __restrict__ bx1,
          const float* __restrict__ Wx2, const float* __restrict__ bx2,
          const float* __restrict__ Wh1, const float* __restrict__ bh1,
          const float* __restrict__ Wh2, const float* __restrict__ bh2,
          float* __restrict__ out) {
    extern __shared__ uint32_t sm[];
    uint32_t* Ts   = sm;
    uint32_t* Wf2  = sm + 18432;
    uint32_t* Wf1  = sm + 20480;
    float* xs      = (float*)(sm + 22528);
    float* fmisc   = (float*)(sm + 25600);
    float* biasf2  = fmisc;         // 64
    float* biasf1  = fmisc + 64;    // 64
    float* wx2f    = fmisc + 128;   // 64
    float* wdwa    = fmisc + 192;   // 128
    float* Pi_s    = fmisc + 320;   // 64
    float* s_sh    = fmisc + 384;   // 512
    float* mired   = fmisc + 896;   // 16*64 = 1024
    float* mi_s    = fmisc + 1920;  // 64
    float* hids    = fmisc + 1984;  // 64
    float* xred    = fmisc + 2048;  // 48

    const int tid  = threadIdx.x;
    const int lane = tid & 31;
    const int warp = tid >> 5;
    const int wrow = warp << 5;
    const int g    = lane >> 2;
    const int t4   = lane & 3;

    // ---- one-time staging (persistent CTA) ----
    for (int idx = tid; idx < 4096; idx += NTH) {
        int k = idx >> 6, n = idx & 63;
        int kt = k >> 4, tt = (k >> 1) & 3, hi = (k >> 3) & 1, lo = k & 1;
        int np = n >> 4, s2 = (n >> 3) & 1, gg = n & 7;
        int dst = (((kt * 4 + np) * 32 + (gg * 4 + tt)) * 4 + s2 * 2 + hi) * 2 + lo;
        ((__half*)Wf2)[dst] = __float2half(We2[idx]);
        ((__half*)Wf1)[dst] = __float2half(Wx1[idx]);
    }
    for (int idx = tid; idx < 3072; idx += NTH) xs[idx] = x[idx];
    if (tid < 64) {
        int nt = tid >> 3, u = tid & 7;
        int dst = (u >> 1) * 16 + nt * 2 + (u & 1);
        biasf2[dst] = be2[tid];
        biasf1[dst] = bx1[tid];
        wx2f[dst]   = Wx2[tid];
        wdwa[(tid >> 2) * 8 + (tid & 3)]     = We1[128 * 64 + tid];
        wdwa[(tid >> 2) * 8 + 4 + (tid & 3)] = We1[129 * 64 + tid];
    }
    __syncthreads();

    const float bx2v = bx2[0];
    const float C = 1.0f / (float)(M_NODES - 1);

    for (int i = blockIdx.x; i < M_NODES; i += NBLK) {
        __syncthreads();   // s_sh/Pi_s/mired reuse from previous i
        if (tid < 64) Pi_s[tid] = g_Pi[i * 64 + tid];
        __syncthreads();

        const float xi0 = xs[i * 3 + 0];
        const float xi1 = xs[i * 3 + 1];
        const float xi2 = xs[i * 3 + 2];
        const float* arow = a + (size_t)i * M_NODES;

        float macc[16];
#pragma unroll
        for (int q = 0; q < 16; q++) macc[q] = 0.f;
        float xa0 = 0.f, xa1 = 0.f, xa2 = 0.f;

        for (int jb = 0; jb < M_NODES; jb += TJ) {
            __syncwarp();   // Ts/s_sh reuse (warp-local rows)
            const int j = jb + tid;
            const float dx0 = xi0 - xs[j * 3 + 0];
            const float dx1 = xi1 - xs[j * 3 + 1];
            const float dx2 = xi2 - xs[j * 3 + 2];
            const float d2  = dx0 * dx0 + dx1 * dx1 + dx2 * dx2;
            const float aij = arow[j];

            // ---- phase 1: t = silu(pre) -> Ts (half2, natural k order) ----
            const float4* pjr = (const float4*)(g_Pj + j * 64);
            uint4* trow = (uint4*)(Ts + tid * TS36);
#pragma unroll
            for (int k8 = 0; k8 < 8; k8++) {
                float v[8];
#pragma unroll
                for (int q = 0; q < 2; q++) {
                    int k4 = k8 * 2 + q;
                    float4 pj = pjr[k4];
                    float4 pi = *(const float4*)&Pi_s[k4 * 4];
                    float4 wd = *(const float4*)&wdwa[k4 * 8];
                    float4 wa = *(const float4*)&wdwa[k4 * 8 + 4];
                    v[q*4+0] = silu_t(fmaf(aij, wa.x, fmaf(d2, wd.x, pi.x + pj.x)));
                    v[q*4+1] = silu_t(fmaf(aij, wa.y, fmaf(d2, wd.y, pi.y + pj.y)));
                    v[q*4+2] = silu_t(fmaf(aij, wa.z, fmaf(d2, wd.z, pi.z + pj.z)));
                    v[q*4+3] = silu_t(fmaf(aij, wa.w, fmaf(d2, wd.w, pi.w + pj.w)));
                }
                uint4 o;
                o.x = h2(v[0], v[1]); o.y = h2(v[2], v[3]);
                o.z = h2(v[4], v[5]); o.w = h2(v[6], v[7]);
                trow[k8] = o;
            }
            __syncwarp();

            // ---- gemm1: m_pre = T @ We2 + be2 ----
            float acc[2][8][4];
            do_gemm(Ts, Wf2, biasf2, acc, wrow, g, t4, lane);
            __syncwarp();

            // ---- epilogue1: m = silu; macc; Ts <- half2(m) ----
#pragma unroll
            for (int mt = 0; mt < 2; mt++) {
                const int e0 = wrow + mt * 16 + g;
                const int e1 = e0 + 8;
                const bool d0 = (jb + e0) == i;
                const bool d1 = (jb + e1) == i;
#pragma unroll
                for (int nt = 0; nt < 8; nt++) {
                    float m0 = silu_t(acc[mt][nt][0]);
                    float m1 = silu_t(acc[mt][nt][1]);
                    float m2 = silu_t(acc[mt][nt][2]);
                    float m3 = silu_t(acc[mt][nt][3]);
                    if (!d0) { macc[nt*2] += m0; macc[nt*2+1] += m1; }
                    if (!d1) { macc[nt*2] += m2; macc[nt*2+1] += m3; }
                    Ts[e0 * TS36 + nt * 4 + t4] = h2(m0, m1);
                    Ts[e1 * TS36 + nt * 4 + t4] = h2(m2, m3);
                }
            }
            __syncwarp();

            // ---- gemm2: u_pre = M @ Wx1 + bx1 ----
            do_gemm(Ts, Wf1, biasf1, acc, wrow, g, t4, lane);

            // ---- epilogue2: s = silu(u) . Wx2 + bx2 ----
            const float4* wxf = (const float4*)(wx2f + t4 * 16);
            float sp0 = 0.f, sp1 = 0.f, sp2 = 0.f, sp3 = 0.f;
#pragma unroll
            for (int np = 0; np < 4; np++) {
                float4 w = wxf[np];
#pragma unroll
                for (int mt = 0; mt < 2; mt++) {
                    float u0 = silu_t(acc[mt][2*np][0]);
                    float u1 = silu_t(acc[mt][2*np][1]);
                    float u2 = silu_t(acc[mt][2*np][2]);
                    float u3 = silu_t(acc[mt][2*np][3]);
                    float lo = fmaf(u0, w.x, u1 * w.y);
                    float hi = fmaf(u2, w.x, u3 * w.y);
                    float u4 = silu_t(acc[mt][2*np+1][0]);
                    float u5 = silu_t(acc[mt][2*np+1][1]);
                    float u6 = silu_t(acc[mt][2*np+1][2]);
                    float u7 = silu_t(acc[mt][2*np+1][3]);
                    lo = fmaf(u4, w.z, fmaf(u5, w.w, lo));
                    hi = fmaf(u6, w.z, fmaf(u7, w.w, hi));
                    if (mt == 0) { sp0 += lo; sp1 += hi; }
                    else         { sp2 += lo; sp3 += hi; }
                }
            }
            sp0 += __shfl_xor_sync(0xffffffffu, sp0, 1);
            sp0 += __shfl_xor_sync(0xffffffffu, sp0, 2);
            sp1 += __shfl_xor_sync(0xffffffffu, sp1, 1);
            sp1 += __shfl_xor_sync(0xffffffffu, sp1, 2);
            sp2 += __shfl_xor_sync(0xffffffffu, sp2, 1);
            sp2 += __shfl_xor_sync(0xffffffffu, sp2, 2);
            sp3 += __shfl_xor_sync(0xffffffffu, sp3, 1);
            sp3 += __shfl_xor_sync(0xffffffffu, sp3, 2);
            if (t4 == 0) {
                s_sh[wrow + g]      = sp0 + bx2v;
                s_sh[wrow + 8 + g]  = sp1 + bx2v;
                s_sh[wrow + 16 + g] = sp2 + bx2v;
                s_sh[wrow + 24 + g] = sp3 + bx2v;
            }
            __syncwarp();

            // ---- phase 4: coordinate accumulation ----
            float s = s_sh[tid];
            if (j != i) {
                xa0 = fmaf(dx0, s, xa0);
                xa1 = fmaf(dx1, s, xa1);
                xa2 = fmaf(dx2, s, xa2);
            }
        }

        // ---- macc: reduce over g within warp, write per-warp partials ----
#pragma unroll
        for (int q = 0; q < 16; q++) {
            macc[q] += __shfl_xor_sync(0xffffffffu, macc[q], 4);
            macc[q] += __shfl_xor_sync(0xffffffffu, macc[q], 8);
            macc[q] += __shfl_xor_sync(0xffffffffu, macc[q], 16);
        }
        if (lane < 4) {
#pragma unroll
            for (int nt = 0; nt < 8; nt++) {
                mired[warp * 64 + nt * 8 + lane * 2]     = macc[nt * 2];
                mired[warp * 64 + nt * 8 + lane * 2 + 1] = macc[nt * 2 + 1];
            }
        }
#pragma unroll
        for (int o = 16; o >= 1; o >>= 1) {
            xa0 += __shfl_xor_sync(0xffffffffu, xa0, o);
            xa1 += __shfl_xor_sync(0xffffffffu, xa1, o);
            xa2 += __shfl_xor_sync(0xffffffffu, xa2, o);
        }
        if (lane == 0) {
            xred[warp * 3 + 0] = xa0;
            xred[warp * 3 + 1] = xa1;
            xred[warp * 3 + 2] = xa2;
        }
        __syncthreads();

        if (tid < 64) {
            float s = 0.f;
#pragma unroll
            for (int w = 0; w < 16; w++) s += mired[w * 64 + tid];
            mi_s[tid] = s;
        }
        if (tid < 3) {
            float s = 0.f;
#pragma unroll
            for (int w = 0; w < 16; w++) s += xred[w * 3 + tid];
            out[i * 3 + tid] = fmaf(C, s, xs[i * 3 + tid]);
        }
        __syncthreads();

        // ---- h_new: 2-layer MLP (weights from L2; per-i cost is tiny) ----
        if (tid < 256) {
            const int c = tid & 63, p = tid >> 6;
            float a1 = 0.f;
            if (p < 2) {
                const float* hr = h + i * 64 + p * 32;
                const float* wr = Wh1 + (p * 32) * 64 + c;
#pragma unroll 8
                for (int q = 0; q < 32; q++) a1 = fmaf(hr[q], wr[q * 64], a1);
            } else {
                const float* mr = mi_s + (p - 2) * 32;
                const float* wr = Wh1 + (64 + (p - 2) * 32) * 64 + c;
#pragma unroll 8
                for (int q = 0; q < 32; q++) a1 = fmaf(mr[q], wr[q * 64], a1);
            }
            s_sh[tid] = a1;
        }
        __syncthreads();
        if (tid < 64)
            hids[tid] = silu_t(bh1[tid] + s_sh[tid] + s_sh[64 + tid] +
                               s_sh[128 + tid] + s_sh[192 + tid]);
        __syncthreads();
        if (tid < 256) {
            const int c = tid & 63, p = tid >> 6;
            float a2 = 0.f;
            const float* hp = hids + p * 16;
            const float* wr = Wh2 + (p * 16) * 64 + c;
#pragma unroll 8
            for (int q = 0; q < 16; q++) a2 = fmaf(hp[q], wr[q * 64], a2);
            s_sh[tid] = a2;
        }
        __syncthreads();
        if (tid < 64)
            out[3 * M_NODES + i * 64 + tid] =
                bh2[tid] + s_sh[tid] + s_sh[64 + tid] + s_sh[128 + tid] + s_sh[192 + tid];
    }
}

extern "C" void kernel_launch(void* const* d_in, const int* in_sizes, int n_in,
                              void* d_out, int out_size) {
    const float* x   = (const float*)d_in[0];
    const float* a   = (const float*)d_in[1];
    const float* h   = (const float*)d_in[2];
    const float* We1 = (const float*)d_in[3];
    const float* be1 = (const float*)d_in[4];
    const float* We2 = (const float*)d_in[5];
    const float* be2 = (const float*)d_in[6];
    const float* Wx1 = (const float*)d_in[7];
    const float* bx1 = (const float*)d_in[8];
    const float* Wx2 = (const float*)d_in[9];
    const float* bx2 = (const float*)d_in[10];
    const float* Wh1 = (const float*)d_in[11];
    const float* bh1 = (const float*)d_in[12];
    const float* Wh2 = (const float*)d_in[13];
    const float* bh2 = (const float*)d_in[14];
    float* out = (float*)d_out;

    cudaFuncSetAttribute(ecnn_main, cudaFuncAttributeMaxDynamicSharedMemorySize,
                         SMEM_BYTES);

    prep_kernel<<<(M_NODES * 64) / 256, 256>>>(h, We1, be1);
    ecnn_main<<<NBLK, NTH, SMEM_BYTES>>>(
        x, a, h, We1, We2, be2, Wx1, bx1, Wx2, bx2, Wh1, bh1, Wh2, bh2, out);
}

// round 7
// speedup vs baseline: 4.4008x; 1.0272x over previous
#include <cuda_runtime.h>
#include <cuda_fp16.h>
#include <cstdint>

#define M_NODES 1024
#define NTH 512
#define TJ 512
#define NBLK 148
#define TS36 36   // Ts row stride in u32 (32 data + 4 pad -> conflict-free)

// scratch (no cudaMalloc allowed)
__device__ float g_Pi[M_NODES * 64];
__device__ float g_Pj[M_NODES * 64];

// ---- half2 helpers --------------------------------------------------------
__device__ __forceinline__ uint32_t packh2(float lo, float hi) {
    uint32_t r;
    asm("cvt.rn.f16x2.f32 %0, %1, %2;" : "=r"(r) : "f"(hi), "f"(lo));
    return r;
}
__device__ __forceinline__ float2 uph2(uint32_t v) {
    __half2 h; *(uint32_t*)&h = v;
    return __half22float2(h);
}
__device__ __forceinline__ uint32_t hfma2v(uint32_t a, uint32_t b, uint32_t c) {
    uint32_t d;
    asm("fma.rn.f16x2 %0, %1, %2, %3;" : "=r"(d) : "r"(a), "r"(b), "r"(c));
    return d;
}
// silu on a packed half2: hx = 0.5*p; t = tanh(hx); res = hx*t + hx
__device__ __forceinline__ uint32_t silu2h(uint32_t p2) {
    uint32_t hx, t;
    const uint32_t H05 = 0x38003800u;  // half2(0.5, 0.5)
    asm("mul.rn.f16x2 %0, %1, %2;" : "=r"(hx) : "r"(p2), "r"(H05));
    asm("tanh.approx.f16x2 %0, %1;" : "=r"(t) : "r"(hx));
    return hfma2v(hx, t, hx);
}
// scalar f32 silu for the tiny h-epilogue
__device__ __forceinline__ float silu_t(float v) {
    float hx = 0.5f * v;
    float t;
    asm("tanh.approx.f32 %0, %1;" : "=f"(t) : "f"(hx));
    return fmaf(hx, t, hx);
}

__device__ __forceinline__ void mma16(float* c, const uint32_t* a, const uint32_t* b) {
    asm volatile(
        "mma.sync.aligned.m16n8k16.row.col.f32.f16.f16.f32 "
        "{%0,%1,%2,%3}, {%4,%5,%6,%7}, {%8,%9}, {%0,%1,%2,%3};"
        : "+f"(c[0]), "+f"(c[1]), "+f"(c[2]), "+f"(c[3])
        : "r"(a[0]), "r"(a[1]), "r"(a[2]), "r"(a[3]), "r"(b[0]), "r"(b[1]));
}
__device__ __forceinline__ void ldsm4(uint32_t* r, uint32_t addr) {
    asm volatile("ldmatrix.sync.aligned.m8n8.x4.shared.b16 {%0,%1,%2,%3}, [%4];"
        : "=r"(r[0]), "=r"(r[1]), "=r"(r[2]), "=r"(r[3]) : "r"(addr));
}

// ---------------------------------------------------------------------------
__global__ void prep_kernel(const float* __restrict__ h,
                            const float* __restrict__ We1,
                            const float* __restrict__ be1) {
    int idx = blockIdx.x * blockDim.x + threadIdx.x;
    int i = idx >> 6, c = idx & 63;
    const float* hr = h + i * 64;
    float pi = be1[c], pj = 0.f;
#pragma unroll 16
    for (int k = 0; k < 64; k++) {
        float hv = hr[k];
        pi = fmaf(hv, We1[k * 64 + c], pi);
        pj = fmaf(hv, We1[(64 + k) * 64 + c], pj);
    }
    g_Pi[idx] = pi;
    g_Pj[idx] = pj;
}

// ---------------------------------------------------------------------------
// Warp-GEMM (fp16 m16n8k16): A via ldmatrix.x4 from Ts (row stride 144B),
// B from fragment-ordered half weights Wf (lane-consecutive uint4),
// bias in fragment order biasf[t4*16 + nt*2 + s].
// ---------------------------------------------------------------------------
__device__ __forceinline__ void do_gemm(const uint32_t* __restrict__ Wf,
                                        const float* __restrict__ biasf,
                                        float acc[2][8][4],
                                        uint32_t a_addr, int t4, int lane) {
    const float4* bf = (const float4*)(biasf + t4 * 16);
#pragma unroll
    for (int np = 0; np < 4; np++) {
        float4 b = bf[np];
#pragma unroll
        for (int mt = 0; mt < 2; mt++) {
            acc[mt][2*np][0] = b.x; acc[mt][2*np][1] = b.y;
            acc[mt][2*np][2] = b.x; acc[mt][2*np][3] = b.y;
            acc[mt][2*np+1][0] = b.z; acc[mt][2*np+1][1] = b.w;
            acc[mt][2*np+1][2] = b.z; acc[mt][2*np+1][3] = b.w;
        }
    }
#pragma unroll
    for (int kt = 0; kt < 4; kt++) {
        uint32_t A0[4], A1[4];
        ldsm4(A0, a_addr + kt * 32);
        ldsm4(A1, a_addr + 16 * 144 + kt * 32);
#pragma unroll
        for (int np = 0; np < 4; np++) {
            uint4 Bv = ((const uint4*)Wf)[(kt * 4 + np) * 32 + lane];
            uint32_t B0[2] = {Bv.x, Bv.y};
            uint32_t B1[2] = {Bv.z, Bv.w};
            mma16(acc[0][2*np],   A0, B0);
            mma16(acc[1][2*np],   A1, B0);
            mma16(acc[0][2*np+1], A0, B1);
            mma16(acc[1][2*np+1], A1, B1);
        }
    }
}

// ---------------------------------------------------------------------------
// Persistent fused kernel: 148 CTAs x 512 threads (16 warps).
// Per i: j-tile of 512 -> 2 iterations; warp w owns tile rows [32w, 32w+32):
// the j-loop is fully warp-synchronous (zero __syncthreads inside).
// ---------------------------------------------------------------------------
// SMEM (u32 words):
// Ts 512*36=18432 | Wf2 2048 | Wf1 2048 | xs 3072 | fmisc 2160 = 27760 words
#define SMEM_BYTES (27760 * 4)

__global__ void __launch_bounds__(NTH, 1)
ecnn_main(const float* __restrict__ x, const float* __restrict__ a,
          const float* __restrict__ h, const float* __restrict__ We1,
          const float* __restrict__ We2, const float* __restrict__ be2,
          const float* __restrict__ Wx1, const float* __restrict__ bx1,
          const float* __restrict__ Wx2, const float* __restrict__ bx2,
          const float* __restrict__ Wh1, const float* __restrict__ bh1,
          const float* __restrict__ Wh2, const float* __restrict__ bh2,
          float* __restrict__ out) {
    extern __shared__ uint32_t sm[];
    uint32_t* Ts   = sm;
    uint32_t* Wf2  = sm + 18432;
    uint32_t* Wf1  = sm + 20480;
    float* xs      = (float*)(sm + 22528);
    float* fmisc   = (float*)(sm + 25600);
    float* biasf2  = fmisc;         // 64
    float* biasf1  = fmisc + 64;    // 64
    float* wx2f    = fmisc + 128;   // 64
    float* wdwa    = fmisc + 192;   // 128
    float* Pi_s    = fmisc + 320;   // 64
    float* s_sh    = fmisc + 384;   // 512
    float* mired   = fmisc + 896;   // 16*64 = 1024
    float* mi_s    = fmisc + 1920;  // 64
    float* hids    = fmisc + 1984;  // 64
    float* xred    = fmisc + 2048;  // 48

    const int tid  = threadIdx.x;
    const int lane = tid & 31;
    const int warp = tid >> 5;
    const int wrow = warp << 5;
    const int g    = lane >> 2;
    const int t4   = lane & 3;

    // ldmatrix source address (lane-fixed): rows of this warp's A tile
    const int lrow = (lane & 7) + ((lane >> 3) & 1) * 8;
    const uint32_t ts_sh = (uint32_t)__cvta_generic_to_shared(Ts);
    const uint32_t a_addr = ts_sh + (uint32_t)(wrow + lrow) * 144u
                                  + (uint32_t)((lane >> 4) & 1) * 16u;

    // ---- one-time staging (persistent CTA) ----
    for (int idx = tid; idx < 4096; idx += NTH) {
        int k = idx >> 6, n = idx & 63;
        int kt = k >> 4, tt = (k >> 1) & 3, hi = (k >> 3) & 1, lo = k & 1;
        int np = n >> 4, s2 = (n >> 3) & 1, gg = n & 7;
        int dst = (((kt * 4 + np) * 32 + (gg * 4 + tt)) * 4 + s2 * 2 + hi) * 2 + lo;
        ((__half*)Wf2)[dst] = __float2half(We2[idx]);
        ((__half*)Wf1)[dst] = __float2half(Wx1[idx]);
    }
    for (int idx = tid; idx < 3072; idx += NTH) xs[idx] = x[idx];
    if (tid < 64) {
        int nt = tid >> 3, u = tid & 7;
        int dst = (u >> 1) * 16 + nt * 2 + (u & 1);
        biasf2[dst] = be2[tid];
        biasf1[dst] = bx1[tid];
        wx2f[dst]   = Wx2[tid];
        wdwa[(tid >> 2) * 8 + (tid & 3)]     = We1[128 * 64 + tid];
        wdwa[(tid >> 2) * 8 + 4 + (tid & 3)] = We1[129 * 64 + tid];
    }
    __syncthreads();

    // pack wx2 fragment into half2 registers (loop-invariant)
    uint32_t wxh[4][2];
    {
        const float4* wxf = (const float4*)(wx2f + t4 * 16);
#pragma unroll
        for (int np = 0; np < 4; np++) {
            float4 w = wxf[np];
            wxh[np][0] = packh2(w.x, w.y);
            wxh[np][1] = packh2(w.z, w.w);
        }
    }

    const float bx2v = bx2[0];
    const float C = 1.0f / (float)(M_NODES - 1);

    for (int i = blockIdx.x; i < M_NODES; i += NBLK) {
        const float* arow = a + (size_t)i * M_NODES;
        // prefetch this i's adjacency entries early (L2 latency hiding)
        const float aij0 = arow[tid];
        const float aij1 = arow[TJ + tid];

        __syncthreads();   // s_sh/Pi_s/mired reuse from previous i
        if (tid < 64) Pi_s[tid] = g_Pi[i * 64 + tid];
        __syncthreads();

        const float xi0 = xs[i * 3 + 0];
        const float xi1 = xs[i * 3 + 1];
        const float xi2 = xs[i * 3 + 2];

        float macc[16];
#pragma unroll
        for (int q = 0; q < 16; q++) macc[q] = 0.f;
        float xa0 = 0.f, xa1 = 0.f, xa2 = 0.f;

#pragma unroll
        for (int jb = 0; jb < M_NODES; jb += TJ) {
            __syncwarp();   // Ts/s_sh reuse (warp-local rows)
            const int j = jb + tid;
            const float dx0 = xi0 - xs[j * 3 + 0];
            const float dx1 = xi1 - xs[j * 3 + 1];
            const float dx2 = xi2 - xs[j * 3 + 2];
            const float d2  = dx0 * dx0 + dx1 * dx1 + dx2 * dx2;
            const float aij = (jb == 0) ? aij0 : aij1;

            // ---- phase 1: t = silu(pre) in half2 -> Ts ----
            const float4* pjr = (const float4*)(g_Pj + j * 64);
            uint4* trow = (uint4*)(Ts + tid * TS36);
#pragma unroll
            for (int k8 = 0; k8 < 8; k8++) {
                float p[8];
#pragma unroll
                for (int q = 0; q < 2; q++) {
                    int k4 = k8 * 2 + q;
                    float4 pj = pjr[k4];
                    float4 pi = *(const float4*)&Pi_s[k4 * 4];
                    float4 wd = *(const float4*)&wdwa[k4 * 8];
                    float4 wa = *(const float4*)&wdwa[k4 * 8 + 4];
                    p[q*4+0] = fmaf(aij, wa.x, fmaf(d2, wd.x, pi.x + pj.x));
                    p[q*4+1] = fmaf(aij, wa.y, fmaf(d2, wd.y, pi.y + pj.y));
                    p[q*4+2] = fmaf(aij, wa.z, fmaf(d2, wd.z, pi.z + pj.z));
                    p[q*4+3] = fmaf(aij, wa.w, fmaf(d2, wd.w, pi.w + pj.w));
                }
                uint4 o;
                o.x = silu2h(packh2(p[0], p[1]));
                o.y = silu2h(packh2(p[2], p[3]));
                o.z = silu2h(packh2(p[4], p[5]));
                o.w = silu2h(packh2(p[6], p[7]));
                trow[k8] = o;
            }
            __syncwarp();

            // ---- gemm1: m_pre = T @ We2 + be2 ----
            float acc[2][8][4];
            do_gemm(Wf2, biasf2, acc, a_addr, t4, lane);
            __syncwarp();

            // ---- epilogue1: m = silu (half2); macc (f32); Ts <- m ----
#pragma unroll
            for (int mt = 0; mt < 2; mt++) {
                const int e0 = wrow + mt * 16 + g;
                const int e1 = e0 + 8;
                const bool d0 = (jb + e0) == i;
                const bool d1 = (jb + e1) == i;
#pragma unroll
                for (int nt = 0; nt < 8; nt++) {
                    uint32_t h0 = silu2h(packh2(acc[mt][nt][0], acc[mt][nt][1]));
                    uint32_t h1 = silu2h(packh2(acc[mt][nt][2], acc[mt][nt][3]));
                    float2 f0 = uph2(h0);
                    float2 f1 = uph2(h1);
                    if (!d0) { macc[nt*2] += f0.x; macc[nt*2+1] += f0.y; }
                    if (!d1) { macc[nt*2] += f1.x; macc[nt*2+1] += f1.y; }
                    Ts[e0 * TS36 + nt * 4 + t4] = h0;
                    Ts[e1 * TS36 + nt * 4 + t4] = h1;
                }
            }
            __syncwarp();

            // ---- gemm2: u_pre = M @ Wx1 + bx1 ----
            do_gemm(Wf1, biasf1, acc, a_addr, t4, lane);

            // ---- epilogue2: s = silu(u) . Wx2 + bx2 (half2 dot) ----
            uint32_t se0a = 0, se1a = 0, se0b = 0, se1b = 0;
#pragma unroll
            for (int np = 0; np < 4; np++) {
#pragma unroll
                for (int mt = 0; mt < 2; mt++) {
                    uint32_t u01e0 = silu2h(packh2(acc[mt][2*np][0],   acc[mt][2*np][1]));
                    uint32_t u01e1 = silu2h(packh2(acc[mt][2*np][2],   acc[mt][2*np][3]));
                    uint32_t u23e0 = silu2h(packh2(acc[mt][2*np+1][0], acc[mt][2*np+1][1]));
                    uint32_t u23e1 = silu2h(packh2(acc[mt][2*np+1][2], acc[mt][2*np+1][3]));
                    if (mt == 0) {
                        se0a = hfma2v(u01e0, wxh[np][0], se0a);
                        se0a = hfma2v(u23e0, wxh[np][1], se0a);
                        se1a = hfma2v(u01e1, wxh[np][0], se1a);
                        se1a = hfma2v(u23e1, wxh[np][1], se1a);
                    } else {
                        se0b = hfma2v(u01e0, wxh[np][0], se0b);
                        se0b = hfma2v(u23e0, wxh[np][1], se0b);
                        se1b = hfma2v(u01e1, wxh[np][0], se1b);
                        se1b = hfma2v(u23e1, wxh[np][1], se1b);
                    }
                }
            }
            float2 fr;
            fr = uph2(se0a); float sp0 = fr.x + fr.y;
            fr = uph2(se1a); float sp1 = fr.x + fr.y;
            fr = uph2(se0b); float sp2 = fr.x + fr.y;
            fr = uph2(se1b); float sp3 = fr.x + fr.y;

            sp0 += __shfl_xor_sync(0xffffffffu, sp0, 1);
            sp0 += __shfl_xor_sync(0xffffffffu, sp0, 2);
            sp1 += __shfl_xor_sync(0xffffffffu, sp1, 1);
            sp1 += __shfl_xor_sync(0xffffffffu, sp1, 2);
            sp2 += __shfl_xor_sync(0xffffffffu, sp2, 1);
            sp2 += __shfl_xor_sync(0xffffffffu, sp2, 2);
            sp3 += __shfl_xor_sync(0xffffffffu, sp3, 1);
            sp3 += __shfl_xor_sync(0xffffffffu, sp3, 2);
            if (t4 == 0) {
                s_sh[wrow + g]      = sp0 + bx2v;
                s_sh[wrow + 8 + g]  = sp1 + bx2v;
                s_sh[wrow + 16 + g] = sp2 + bx2v;
                s_sh[wrow + 24 + g] = sp3 + bx2v;
            }
            __syncwarp();

            // ---- phase 4: coordinate accumulation ----
            float s = s_sh[tid];
            if (j != i) {
                xa0 = fmaf(dx0, s, xa0);
                xa1 = fmaf(dx1, s, xa1);
                xa2 = fmaf(dx2, s, xa2);
            }
        }

        // ---- macc: reduce over g within warp, write per-warp partials ----
#pragma unroll
        for (int q = 0; q < 16; q++) {
            macc[q] += __shfl_xor_sync(0xffffffffu, macc[q], 4);
            macc[q] += __shfl_xor_sync(0xffffffffu, macc[q], 8);
            macc[q] += __shfl_xor_sync(0xffffffffu, macc[q], 16);
        }
        if (lane < 4) {
#pragma unroll
            for (int nt = 0; nt < 8; nt++) {
                mired[warp * 64 + nt * 8 + lane * 2]     = macc[nt * 2];
                mired[warp * 64 + nt * 8 + lane * 2 + 1] = macc[nt * 2 + 1];
            }
        }
#pragma unroll
        for (int o = 16; o >= 1; o >>= 1) {
            xa0 += __shfl_xor_sync(0xffffffffu, xa0, o);
            xa1 += __shfl_xor_sync(0xffffffffu, xa1, o);
            xa2 += __shfl_xor_sync(0xffffffffu, xa2, o);
        }
        if (lane == 0) {
            xred[warp * 3 + 0] = xa0;
            xred[warp * 3 + 1] = xa1;
            xred[warp * 3 + 2] = xa2;
        }
        __syncthreads();

        if (tid < 64) {
            float s = 0.f;
#pragma unroll
            for (int w = 0; w < 16; w++) s += mired[w * 64 + tid];
            mi_s[tid] = s;
        }
        if (tid < 3) {
            float s = 0.f;
#pragma unroll
            for (int w = 0; w < 16; w++) s += xred[w * 3 + tid];
            out[i * 3 + tid] = fmaf(C, s, xs[i * 3 + tid]);
        }
        __syncthreads();

        // ---- h_new: 2-layer MLP (weights from L2; per-i cost is tiny) ----
        if (tid < 256) {
            const int c = tid & 63, p = tid >> 6;
            float a1 = 0.f;
            if (p < 2) {
                const float* hr = h + i * 64 + p * 32;
                const float* wr = Wh1 + (p * 32) * 64 + c;
#pragma unroll 8
                for (int q = 0; q < 32; q++) a1 = fmaf(hr[q], wr[q * 64], a1);
            } else {
                const float* mr = mi_s + (p - 2) * 32;
                const float* wr = Wh1 + (64 + (p - 2) * 32) * 64 + c;
#pragma unroll 8
                for (int q = 0; q < 32; q++) a1 = fmaf(mr[q], wr[q * 64], a1);
            }
            s_sh[tid] = a1;
        }
        __syncthreads();
        if (tid < 64)
            hids[tid] = silu_t(bh1[tid] + s_sh[tid] + s_sh[64 + tid] +
                               s_sh[128 + tid] + s_sh[192 + tid]);
        __syncthreads();
        if (tid < 256) {
            const int c = tid & 63, p = tid >> 6;
            float a2 = 0.f;
            const float* hp = hids + p * 16;
            const float* wr = Wh2 + (p * 16) * 64 + c;
#pragma unroll 8
            for (int q = 0; q < 16; q++) a2 = fmaf(hp[q], wr[q * 64], a2);
            s_sh[tid] = a2;
        }
        __syncthreads();
        if (tid < 64)
            out[3 * M_NODES + i * 64 + tid] =
                bh2[tid] + s_sh[tid] + s_sh[64 + tid] + s_sh[128 + tid] + s_sh[192 + tid];
    }
}

extern "C" void kernel_launch(void* const* d_in, const int* in_sizes, int n_in,
                              void* d_out, int out_size) {
    const float* x   = (const float*)d_in[0];
    const float* a   = (const float*)d_in[1];
    const float* h   = (const float*)d_in[2];
    const float* We1 = (const float*)d_in[3];
    const float* be1 = (const float*)d_in[4];
    const float* We2 = (const float*)d_in[5];
    const float* be2 = (const float*)d_in[6];
    const float* Wx1 = (const float*)d_in[7];
    const float* bx1 = (const float*)d_in[8];
    const float* Wx2 = (const float*)d_in[9];
    const float* bx2 = (const float*)d_in[10];
    const float* Wh1 = (const float*)d_in[11];
    const float* bh1 = (const float*)d_in[12];
    const float* Wh2 = (const float*)d_in[13];
    const float* bh2 = (const float*)d_in[14];
    float* out = (float*)d_out;

    cudaFuncSetAttribute(ecnn_main, cudaFuncAttributeMaxDynamicSharedMemorySize,
                         SMEM_BYTES);

    prep_kernel<<<(M_NODES * 64) / 256, 256>>>(h, We1, be1);
    ecnn_main<<<NBLK, NTH, SMEM_BYTES>>>(
        x, a, h, We1, We2, be2, Wx1, bx1, Wx2, bx2, Wh1, bh1, Wh2, bh2, out);
}